// round 3
// baseline (speedup 1.0000x reference)
#include <cuda_runtime.h>
#include <cstdint>
#include <cmath>

typedef unsigned long long ull;

#define DM 768
#define NQ 256
#define NM 512

#define FMA2(acc, a, b) asm("fma.rn.f32x2 %0, %1, %2, %0;" : "+l"(acc) : "l"(a), "l"(b))
#define DUP2(d, s)      asm("mov.b64 %0, {%1, %1};" : "=l"(d) : "f"(s))
#define UNPK2(lo, hi, s) asm("mov.b64 {%0, %1}, %2;" : "=f"(lo), "=f"(hi) : "l"(s))

// ---------------- scratch (__device__ globals; no allocation allowed) -------
__device__ float g_q  [NQ*DM];
__device__ float g_ip [NM*DM];
__device__ float g_tp [NM*DM];
__device__ float g_qh [NQ*DM];
__device__ float g_kd [NM*DM];
__device__ float g_vd [NM*DM];
__device__ float g_vt [NM*DM];
__device__ float g_W01[DM*256];
__device__ float g_b01[256];
__device__ float g_Ah [NM*8*256];   // [m][h][256]  (from vd = v_img - v_tgt)
__device__ float g_At [NM*8*256];   // [m][h][256]  (from vt)
__device__ float g_Bm [NM*256];     // [m][256]
__device__ float g_w  [NQ*NM*8];    // [n][m][h]

// ---------------- generic multi-GEMM: C = scale*( (A - A2?) @ W + bias ) ----
// 64x64 tile, 64 threads, 8x8 microtile, packed f32x2 accumulation.
struct GDesc {
    const float* A;
    const float* A2;     // optional: compute (A - A2)
    const float* W;      // K x N row-major (ldw)
    const float* bias;   // optional, length N
    float*       C;
    int M, N, K, lda, ldw, ldc;
    float scale;
};
struct GParams { GDesc d[16]; };

__global__ __launch_bounds__(64) void sgemm2(GParams p) {
    GDesc d = p.d[blockIdx.z];
    const int m0 = blockIdx.y * 64, n0 = blockIdx.x * 64;
    if (m0 >= d.M || n0 >= d.N) return;

    __shared__ __align__(16) float As[2][16][64];   // [k][m]
    __shared__ __align__(16) float Bs[2][16][64];   // [k][n]

    const int t = threadIdx.x;
    const int KT = d.K >> 4;

    const float* Ap  = d.A + (size_t)(m0 + t) * d.lda;
    const float* A2p = d.A2 ? d.A2 + (size_t)(m0 + t) * d.lda : nullptr;
    const float* Wp  = d.W + (size_t)(t >> 2) * d.ldw + n0 + (t & 3) * 16;

    float4 aR[4], bR[4];

    // ---- load tile 0 ----
#pragma unroll
    for (int i = 0; i < 4; i++) {
        aR[i] = *(const float4*)(Ap + i * 4);
        bR[i] = *(const float4*)(Wp + i * 4);
    }
    if (A2p) {
#pragma unroll
        for (int i = 0; i < 4; i++) {
            float4 a2 = *(const float4*)(A2p + i * 4);
            aR[i].x -= a2.x; aR[i].y -= a2.y; aR[i].z -= a2.z; aR[i].w -= a2.w;
        }
    }
#pragma unroll
    for (int i = 0; i < 4; i++) {
        As[0][i*4+0][t] = aR[i].x;
        As[0][i*4+1][t] = aR[i].y;
        As[0][i*4+2][t] = aR[i].z;
        As[0][i*4+3][t] = aR[i].w;
        *(float4*)&Bs[0][t >> 2][(t & 3) * 16 + i * 4] = bR[i];
    }
    __syncthreads();

    ull acc[32];
#pragma unroll
    for (int i = 0; i < 32; i++) acc[i] = 0ULL;

    const int aoff = (t & 7) * 8;
    const int boff = (t >> 3) * 8;

    for (int kt = 0; kt < KT; kt++) {
        const int cur = kt & 1;
        const bool more = (kt + 1 < KT);
        if (more) {
            const int kb = (kt + 1) * 16;
#pragma unroll
            for (int i = 0; i < 4; i++) {
                aR[i] = *(const float4*)(Ap + kb + i * 4);
                bR[i] = *(const float4*)(Wp + (size_t)kb * d.ldw + i * 4);
            }
            if (A2p) {
#pragma unroll
                for (int i = 0; i < 4; i++) {
                    float4 a2 = *(const float4*)(A2p + kb + i * 4);
                    aR[i].x -= a2.x; aR[i].y -= a2.y; aR[i].z -= a2.z; aR[i].w -= a2.w;
                }
            }
        }
#pragma unroll
        for (int k = 0; k < 16; k++) {
            ulonglong2 a01 = *(const ulonglong2*)&As[cur][k][aoff];
            ulonglong2 a23 = *(const ulonglong2*)&As[cur][k][aoff + 4];
            float4 b0 = *(const float4*)&Bs[cur][k][boff];
            float4 b1 = *(const float4*)&Bs[cur][k][boff + 4];
            ull ap[4] = {a01.x, a01.y, a23.x, a23.y};
            ull bd[8];
            DUP2(bd[0], b0.x); DUP2(bd[1], b0.y); DUP2(bd[2], b0.z); DUP2(bd[3], b0.w);
            DUP2(bd[4], b1.x); DUP2(bd[5], b1.y); DUP2(bd[6], b1.z); DUP2(bd[7], b1.w);
#pragma unroll
            for (int ip = 0; ip < 4; ip++)
#pragma unroll
                for (int j = 0; j < 8; j++)
                    FMA2(acc[ip * 8 + j], ap[ip], bd[j]);
        }
        if (more) {
            const int nxt = cur ^ 1;
#pragma unroll
            for (int i = 0; i < 4; i++) {
                As[nxt][i*4+0][t] = aR[i].x;
                As[nxt][i*4+1][t] = aR[i].y;
                As[nxt][i*4+2][t] = aR[i].z;
                As[nxt][i*4+3][t] = aR[i].w;
                *(float4*)&Bs[nxt][t >> 2][(t & 3) * 16 + i * 4] = bR[i];
            }
            __syncthreads();
        }
    }

    // ---- epilogue ----
    float bias[8];
    if (d.bias) {
        float4 x = *(const float4*)(d.bias + n0 + boff);
        float4 y = *(const float4*)(d.bias + n0 + boff + 4);
        bias[0]=x.x; bias[1]=x.y; bias[2]=x.z; bias[3]=x.w;
        bias[4]=y.x; bias[5]=y.y; bias[6]=y.z; bias[7]=y.w;
    } else {
#pragma unroll
        for (int j = 0; j < 8; j++) bias[j] = 0.f;
    }
    const int mr = m0 + aoff, nc = n0 + boff;
#pragma unroll
    for (int ip = 0; ip < 4; ip++) {
        float lo[8], hi[8];
#pragma unroll
        for (int j = 0; j < 8; j++) UNPK2(lo[j], hi[j], acc[ip * 8 + j]);
        float* r0 = d.C + (size_t)(mr + ip * 2) * d.ldc + nc;
        float* r1 = r0 + d.ldc;
        float4 o;
        o.x = d.scale*(lo[0]+bias[0]); o.y = d.scale*(lo[1]+bias[1]);
        o.z = d.scale*(lo[2]+bias[2]); o.w = d.scale*(lo[3]+bias[3]);
        *(float4*)r0 = o;
        o.x = d.scale*(lo[4]+bias[4]); o.y = d.scale*(lo[5]+bias[5]);
        o.z = d.scale*(lo[6]+bias[6]); o.w = d.scale*(lo[7]+bias[7]);
        *(float4*)(r0 + 4) = o;
        o.x = d.scale*(hi[0]+bias[0]); o.y = d.scale*(hi[1]+bias[1]);
        o.z = d.scale*(hi[2]+bias[2]); o.w = d.scale*(hi[3]+bias[3]);
        *(float4*)r1 = o;
        o.x = d.scale*(hi[4]+bias[4]); o.y = d.scale*(hi[5]+bias[5]);
        o.z = d.scale*(hi[6]+bias[6]); o.w = d.scale*(hi[7]+bias[7]);
        *(float4*)(r1 + 4) = o;
    }
}

// ---------------- b01 = bo @ W1 + b1 (256 outputs) -------------------------
__global__ void b01_kernel(const float* __restrict__ bo, const float* __restrict__ W1,
                           const float* __restrict__ b1, float* __restrict__ b01) {
    int j = threadIdx.x;   // 256
    float s = b1[j];
#pragma unroll 8
    for (int k = 0; k < DM; k++)
        s = fmaf(bo[k], W1[(size_t)k*256 + j], s);
    b01[j] = s;
}

// ---------------- Bm[m][j] = b01[j] + sum_h At[m][h][j] --------------------
__global__ void reduce_kernel(const float* __restrict__ At, const float* __restrict__ b01,
                              float* __restrict__ Bm) {
    int m = blockIdx.x, j = threadIdx.x;
    float s = b01[j];
#pragma unroll
    for (int h = 0; h < 8; h++)
        s += At[(size_t)m*2048 + h*256 + j];
    Bm[(size_t)m*256 + j] = s;
}

// ---------------- logits: w[n,m,h] = sigmoid( qh[n,h,:] . kd[m,h,:] ) ------
__global__ __launch_bounds__(256) void logits_kernel(const float* __restrict__ qh,
                                                     const float* __restrict__ kd,
                                                     float* __restrict__ wbuf) {
    const int h  = blockIdx.z;
    const int m0 = blockIdx.x * 64, n0 = blockIdx.y * 64;
    __shared__ __align__(16) float Qs[16][68];
    __shared__ __align__(16) float Ks[16][68];

    const int tid = threadIdx.x;
    const int tx = tid & 15, ty = tid >> 4;
    const int lrow = tid >> 2, lc4 = tid & 3;

    const float* qp = qh + (size_t)(n0 + lrow)*DM + h*96 + lc4*4;
    const float* kp = kd + (size_t)(m0 + lrow)*DM + h*96 + lc4*4;

    float acc[4][4];
#pragma unroll
    for (int i = 0; i < 4; i++)
#pragma unroll
        for (int j = 0; j < 4; j++) acc[i][j] = 0.f;

    for (int k0 = 0; k0 < 96; k0 += 16) {
        float4 qv = *(const float4*)(qp + k0);
        float4 kv = *(const float4*)(kp + k0);
        __syncthreads();
        Qs[lc4*4+0][lrow] = qv.x;
        Qs[lc4*4+1][lrow] = qv.y;
        Qs[lc4*4+2][lrow] = qv.z;
        Qs[lc4*4+3][lrow] = qv.w;
        Ks[lc4*4+0][lrow] = kv.x;
        Ks[lc4*4+1][lrow] = kv.y;
        Ks[lc4*4+2][lrow] = kv.z;
        Ks[lc4*4+3][lrow] = kv.w;
        __syncthreads();
#pragma unroll
        for (int k = 0; k < 16; k++) {
            float4 a = *(const float4*)&Qs[k][ty*4];
            float4 b = *(const float4*)&Ks[k][tx*4];
            float ar[4] = {a.x, a.y, a.z, a.w};
            float br[4] = {b.x, b.y, b.z, b.w};
#pragma unroll
            for (int i = 0; i < 4; i++)
#pragma unroll
                for (int j = 0; j < 4; j++)
                    acc[i][j] = fmaf(ar[i], br[j], acc[i][j]);
        }
    }
#pragma unroll
    for (int i = 0; i < 4; i++)
#pragma unroll
        for (int j = 0; j < 4; j++) {
            int n = n0 + ty*4 + i, m = m0 + tx*4 + j;
            float wv = 1.f / (1.f + expf(-acc[i][j]));
            wbuf[((size_t)n*NM + m)*8 + h] = wv;
        }
}

// ---------------- fused tail: h=relu(B+Σw·A); h2=relu(h@W2+b2); tanh -------
__global__ __launch_bounds__(256, 2) void fuse_kernel(
    const float* __restrict__ Abuf, const float* __restrict__ Bbuf,
    const float* __restrict__ wbuf, const float* __restrict__ W2,
    const float* __restrict__ b2, const float* __restrict__ W3,
    const float* __restrict__ b3, float* __restrict__ out) {

    __shared__ __align__(16) float A_s[8*256];
    __shared__ __align__(16) float B_s[256];
    __shared__ __align__(16) float w2s[64*64];   // chunk of 64 j-rows of W2
    __shared__ float b2s[64], W3s[64];
    __shared__ float b3s;

    const int m = blockIdx.x, tid = threadIdx.x;

    // stage A[m] (8x256) and B[m] (256)
    {
        const float4* Ag = (const float4*)(Abuf + (size_t)m*2048);
        float4* A4 = (float4*)A_s;
        A4[tid]       = Ag[tid];
        A4[tid + 256] = Ag[tid + 256];
        B_s[tid] = Bbuf[(size_t)m*256 + tid];
        if (tid < 64) { b2s[tid] = b2[tid]; W3s[tid] = W3[tid]; }
        if (tid == 0) b3s = b3[0];
    }

    const int n = tid;
    const float4* wp = (const float4*)(wbuf + ((size_t)n*NM + m)*8);
    float4 wA = wp[0], wB = wp[1];
    float wr[8] = {wA.x, wA.y, wA.z, wA.w, wB.x, wB.y, wB.z, wB.w};

    ull acc[32];
#pragma unroll
    for (int t = 0; t < 32; t++) acc[t] = 0ULL;

    for (int c = 0; c < 4; c++) {
        __syncthreads();
        {
            const float4* w2g = (const float4*)(W2 + c*4096);
            float4* w2s4 = (float4*)w2s;
#pragma unroll
            for (int r = 0; r < 4; r++) w2s4[tid + r*256] = w2g[tid + r*256];
        }
        __syncthreads();

        for (int jj = 0; jj < 64; jj += 4) {
            const int j = c*64 + jj;
            float4 hb = *(const float4*)&B_s[j];
            float hv[4] = {hb.x, hb.y, hb.z, hb.w};
#pragma unroll
            for (int h = 0; h < 8; h++) {
                float4 a = *(const float4*)&A_s[h*256 + j];
                hv[0] = fmaf(wr[h], a.x, hv[0]);
                hv[1] = fmaf(wr[h], a.y, hv[1]);
                hv[2] = fmaf(wr[h], a.z, hv[2]);
                hv[3] = fmaf(wr[h], a.w, hv[3]);
            }
#pragma unroll
            for (int u = 0; u < 4; u++) {
                float hj = fmaxf(hv[u], 0.f);
                ull hh;
                asm("mov.b64 %0, {%1, %1};" : "=l"(hh) : "f"(hj));
                const ulonglong2* row = (const ulonglong2*)(w2s + (jj + u)*64);
#pragma unroll
                for (int t = 0; t < 16; t++) {
                    ulonglong2 pv = row[t];
                    asm("fma.rn.f32x2 %0, %1, %2, %0;" : "+l"(acc[2*t+0]) : "l"(hh), "l"(pv.x));
                    asm("fma.rn.f32x2 %0, %1, %2, %0;" : "+l"(acc[2*t+1]) : "l"(hh), "l"(pv.y));
                }
            }
        }
    }

    float s = b3s;
#pragma unroll
    for (int t = 0; t < 32; t++) {
        float lo, hi;
        UNPK2(lo, hi, acc[t]);
        lo = fmaxf(lo + b2s[2*t+0], 0.f);
        hi = fmaxf(hi + b2s[2*t+1], 0.f);
        s = fmaf(lo, W3s[2*t+0], s);
        s = fmaf(hi, W3s[2*t+1], s);
    }
    out[(size_t)n*NM + m] = 0.5f * tanhf(s);
}

// ---------------- launch ----------------------------------------------------
extern "C" void kernel_launch(void* const* d_in, const int* in_sizes, int n_in,
                              void* d_out, int out_size) {
    const float* Q   = (const float*)d_in[0];
    const float* IMG = (const float*)d_in[1];
    const float* TGT = (const float*)d_in[2];
    const float* Wq  = (const float*)d_in[3];
    const float* bq  = (const float*)d_in[4];
    const float* Wi  = (const float*)d_in[5];
    const float* bi  = (const float*)d_in[6];
    const float* Wt  = (const float*)d_in[7];
    const float* bt  = (const float*)d_in[8];
    const float* Wiq = (const float*)d_in[9];
    const float* biq = (const float*)d_in[10];
    const float* Wik = (const float*)d_in[11];
    const float* bik = (const float*)d_in[12]; (void)bik; // cancels in k-diff
    const float* Wiv = (const float*)d_in[13];
    const float* biv = (const float*)d_in[14]; (void)biv; // cancels: handled via At path
    const float* Wo  = (const float*)d_in[15];
    const float* bo  = (const float*)d_in[16];
    const float* W1  = (const float*)d_in[17];
    const float* b1  = (const float*)d_in[18];
    const float* W2  = (const float*)d_in[19];
    const float* b2  = (const float*)d_in[20];
    const float* W3  = (const float*)d_in[21];
    const float* b3  = (const float*)d_in[22];
    float* out = (float*)d_out;

    float *q, *ip, *tp, *qh, *kd, *vd, *vt, *W01, *b01, *Ah, *At, *Bm, *wb;
    cudaGetSymbolAddress((void**)&q,   g_q);
    cudaGetSymbolAddress((void**)&ip,  g_ip);
    cudaGetSymbolAddress((void**)&tp,  g_tp);
    cudaGetSymbolAddress((void**)&qh,  g_qh);
    cudaGetSymbolAddress((void**)&kd,  g_kd);
    cudaGetSymbolAddress((void**)&vd,  g_vd);
    cudaGetSymbolAddress((void**)&vt,  g_vt);
    cudaGetSymbolAddress((void**)&W01, g_W01);
    cudaGetSymbolAddress((void**)&b01, g_b01);
    cudaGetSymbolAddress((void**)&Ah,  g_Ah);
    cudaGetSymbolAddress((void**)&At,  g_At);
    cudaGetSymbolAddress((void**)&Bm,  g_Bm);
    cudaGetSymbolAddress((void**)&wb,  g_w);

    const float scale = 1.0f / sqrtf(96.0f);

    // NOTE on biv: attn value term = w*v_img + (1-w)*v_tgt. Writing it as
    // v_tgt + w*(v_img - v_tgt), the biv bias cancels in the diff (vd) and is
    // carried entirely by the vt path (which keeps biv).

    // L1: stage-1 projections + W01 fold (all independent)
    GParams p1 = {};
    p1.d[0] = {Q,   0, Wq, bq, q,   256, 768, 768, 768, 768, 768, 1.f};
    p1.d[1] = {IMG, 0, Wi, bi, ip,  512, 768, 768, 768, 768, 768, 1.f};
    p1.d[2] = {TGT, 0, Wt, bt, tp,  512, 768, 768, 768, 768, 768, 1.f};
    p1.d[3] = {Wo,  0, W1, 0,  W01, 768, 256, 768, 768, 256, 256, 1.f};
    sgemm2<<<dim3(12, 12, 4), 64>>>(p1);

    b01_kernel<<<1, 256>>>(bo, W1, b1, b01);

    // L2: stage-2 projections (k/v bias cancels in diffs)
    GParams p2 = {};
    p2.d[0] = {q,  0,  Wiq, biq, qh, 256, 768, 768, 768, 768, 768, scale};
    p2.d[1] = {ip, tp, Wik, 0,   kd, 512, 768, 768, 768, 768, 768, 1.f};
    p2.d[2] = {ip, tp, Wiv, 0,   vd, 512, 768, 768, 768, 768, 768, 1.f};
    p2.d[3] = {tp, 0,  Wiv, 0,   vt, 512, 768, 768, 768, 768, 768, 1.f};
    sgemm2<<<dim3(12, 8, 4), 64>>>(p2);

    // L3: per-head A[m,h,:] = vd_h @ W01_h  and  At[m,h,:] = vt_h @ W01_h
    // (Bm = sum_h At + b01 is computed by reduce_kernel; avoids a K=768 GEMM)
    // biv contribution to Bm: biv@Wiv... NOTE biv enters v_tgt = tp@Wiv + biv.
    // We dropped biv from vt above, so add it back via b01':
    //   Bm = (vt_nobias + biv)@W01 + b01 = sum_h At + (biv@W01 + b01)
    // b01_kernel computes bo@W1 + b1; we need + biv@W01 = biv@(Wo@W1).
    // Equivalent: (biv@Wo)@W1. Fold into b01 via a second pass below.
    GParams p3 = {};
    for (int h = 0; h < 8; h++) {
        p3.d[h]   = {vd + h*96, 0, W01 + h*96*256, 0, Ah + h*256,
                     512, 256, 96, 768, 256, 2048, 1.f};
        p3.d[8+h] = {vt + h*96, 0, W01 + h*96*256, 0, At + h*256,
                     512, 256, 96, 768, 256, 2048, 1.f};
    }
    sgemm2<<<dim3(4, 8, 16), 64>>>(p3);

    // b01 += biv @ W01  (tiny: 256 threads x 768 fma) — fold biv here
    // Implemented by reusing b01_kernel pattern inline via a lambda-less kernel:
    // (separate kernel below)
    extern __global__ void b01_add_kernel(const float*, const float*, float*);
    b01_add_kernel<<<1, 256>>>(biv, W01, b01);

    // reduce: Bm = b01 + sum_h At
    reduce_kernel<<<NM, 256>>>(At, b01, Bm);

    // L4: attention weights (sigmoid of logit diff)
    logits_kernel<<<dim3(8, 4, 8), 256>>>(qh, kd, wb);

    // L5: fused weighted-combine + MLP tail
    fuse_kernel<<<NM, 256>>>(Ah, Bm, wb, W2, b2, W3, b3, out);
}

// b01 += biv @ W01
__global__ void b01_add_kernel(const float* __restrict__ biv,
                               const float* __restrict__ W01,
                               float* __restrict__ b01) {
    int j = threadIdx.x;   // 256
    float s = 0.f;
#pragma unroll 8
    for (int k = 0; k < DM; k++)
        s = fmaf(biv[k], W01[(size_t)k*256 + j], s);
    b01[j] += s;
}

// round 5
// speedup vs baseline: 1.2576x; 1.2576x over previous
#include <cuda_runtime.h>
#include <cuda_bf16.h>
#include <cstdint>
#include <cmath>

typedef unsigned long long ull;
typedef __nv_bfloat16 bf16;
#define DM 768
#define NQ 256
#define NM 512

#define FMA2(acc, a, b) asm("fma.rn.f32x2 %0, %1, %2, %0;" : "+l"(acc) : "l"(a), "l"(b))
#define DUP2(d, s)      asm("mov.b64 %0, {%1, %1};" : "=l"(d) : "f"(s))
#define UNPK2(lo, hi, s) asm("mov.b64 {%0, %1}, %2;" : "=f"(lo), "=f"(hi) : "l"(s))

__device__ __forceinline__ uint32_t smem_u32(const void* p) {
    uint32_t a;
    asm("{ .reg .u64 t; cvta.to.shared.u64 t, %1; cvt.u32.u64 %0, t; }" : "=r"(a) : "l"(p));
    return a;
}
__device__ __forceinline__ void ldm4(uint32_t* r, uint32_t addr) {
    asm volatile("ldmatrix.sync.aligned.m8n8.x4.shared.b16 {%0,%1,%2,%3}, [%4];"
        : "=r"(r[0]), "=r"(r[1]), "=r"(r[2]), "=r"(r[3]) : "r"(addr));
}
__device__ __forceinline__ void mma16816(float* c, const uint32_t* a, const uint32_t* b) {
    asm volatile("mma.sync.aligned.m16n8k16.row.col.f32.bf16.bf16.f32 "
        "{%0,%1,%2,%3}, {%4,%5,%6,%7}, {%8,%9}, {%0,%1,%2,%3};"
        : "+f"(c[0]), "+f"(c[1]), "+f"(c[2]), "+f"(c[3])
        : "r"(a[0]), "r"(a[1]), "r"(a[2]), "r"(a[3]), "r"(b[0]), "r"(b[1]));
}

// ---------------- scratch ---------------------------------------------------
constexpr size_t F_q   = 0;
constexpr size_t F_ip  = F_q   + 256*768;
constexpr size_t F_tp  = F_ip  + 512*768;
constexpr size_t F_qh  = F_tp  + 512*768;
constexpr size_t F_kd  = F_qh  + 256*768;
constexpr size_t F_vd  = F_kd  + 512*768;
constexpr size_t F_vt  = F_vd  + 512*768;
constexpr size_t F_W01 = F_vt  + 512*768;
constexpr size_t F_b01 = F_W01 + 768*256;
constexpr size_t F_Ah  = F_b01 + 256;
constexpr size_t F_At  = F_Ah  + 512*2048;
constexpr size_t F_Bm  = F_At  + 512*2048;
constexpr size_t F_w   = F_Bm  + 512*256;
constexpr size_t F_END = F_w   + 256*512*8;
__device__ __align__(16) float g_f[F_END];

constexpr size_t B_Qs   = 0;                         // each entry = hi, +size = lo
constexpr size_t B_IMGs = B_Qs   + 2*256*768;
constexpr size_t B_TGTs = B_IMGs + 2*512*768;
constexpr size_t B_Wos  = B_TGTs + 2*512*768;
constexpr size_t B_WqT  = B_Wos  + 2*768*768;
constexpr size_t B_WiT  = B_WqT  + 2*768*768;
constexpr size_t B_WtT  = B_WiT  + 2*768*768;
constexpr size_t B_WiqT = B_WtT  + 2*768*768;
constexpr size_t B_WikT = B_WiqT + 2*768*768;
constexpr size_t B_WivT = B_WikT + 2*768*768;
constexpr size_t B_W1T  = B_WivT + 2*768*768;
constexpr size_t B_qs   = B_W1T  + 2*256*768;
constexpr size_t B_dps  = B_qs   + 2*256*768;
constexpr size_t B_tps  = B_dps  + 2*512*768;
constexpr size_t B_qhs  = B_tps  + 2*512*768;
constexpr size_t B_kds  = B_qhs  + 2*256*768;
constexpr size_t B_vds  = B_kds  + 2*512*768;
constexpr size_t B_vts  = B_vds  + 2*512*768;
constexpr size_t B_W01T = B_vts  + 2*512*768;
constexpr size_t B_END  = B_W01T + 2*256*768;
__device__ __align__(16) bf16 g_b[B_END];

// ---------------- bf16-split MMA GEMM ---------------------------------------
// C[M,N] = scale * (Ah@Bh^T + Ah@Bl^T + Al@Bh^T + bias), A: MxK rm, B: NxK rm.
struct TCDesc {
    const bf16 *Ah, *Al, *Bh, *Bl;
    const float* bias;
    float* C;
    int lda, ldb, ldc, M, N, K;
    float scale;
};
struct TCParams { TCDesc d[16]; };

template<int EPI>
__global__ __launch_bounds__(256) void mma_gemm(TCParams p) {
    TCDesc d = p.d[EPI ? 0 : blockIdx.z];
    const int m0 = blockIdx.y * 128, n0 = blockIdx.x * 64;
    if (m0 >= d.M || n0 >= d.N) return;
    const int hof = EPI ? blockIdx.z * 96 : 0;

    __shared__ __align__(16) bf16 sAh[128][40], sAl[128][40], sBh[64][40], sBl[64][40];

    const int t = threadIdx.x, lane = t & 31, w = t >> 5;
    const int mrow = (w & 3) * 32, ncol = (w >> 2) * 32;

    const int ar = t >> 2, acl = (t & 3) * 8;
    const bf16* pAh = d.Ah + hof + (size_t)(m0 + ar) * d.lda + acl;
    const bf16* pAl = d.Al + hof + (size_t)(m0 + ar) * d.lda + acl;
    const bf16* pBh = d.Bh + hof + (size_t)(n0 + ar) * d.ldb + acl;
    const bf16* pBl = d.Bl + hof + (size_t)(n0 + ar) * d.ldb + acl;
    const size_t a64 = (size_t)64 * d.lda;

    const uint32_t uAh = smem_u32(&sAh[0][0]), uAl = smem_u32(&sAl[0][0]);
    const uint32_t uBh = smem_u32(&sBh[0][0]), uBl = smem_u32(&sBl[0][0]);
    const int aR = mrow + (lane & 15), aC = (lane >> 4) * 8;
    const int bR = ncol + (lane & 7) + ((lane & 16) >> 1), bC = lane & 8;
    uint32_t adAh[2], adAl[2], adBh[2], adBl[2];
#pragma unroll
    for (int mt = 0; mt < 2; mt++) {
        adAh[mt] = uAh + ((aR + mt*16)*40 + aC)*2;
        adAl[mt] = uAl + ((aR + mt*16)*40 + aC)*2;
    }
#pragma unroll
    for (int pr = 0; pr < 2; pr++) {
        adBh[pr] = uBh + ((bR + pr*16)*40 + bC)*2;
        adBl[pr] = uBl + ((bR + pr*16)*40 + bC)*2;
    }

    float acc[2][4][4];
#pragma unroll
    for (int mt = 0; mt < 2; mt++)
#pragma unroll
        for (int nt = 0; nt < 4; nt++)
#pragma unroll
            for (int i = 0; i < 4; i++) acc[mt][nt][i] = 0.f;

    const int nkt = d.K >> 5;
    for (int kt = 0; kt < nkt; kt++) {
        const int k0 = kt * 32;
        uint4 vh0 = *(const uint4*)(pAh + k0);
        uint4 vh1 = *(const uint4*)(pAh + a64 + k0);
        uint4 vl0 = *(const uint4*)(pAl + k0);
        uint4 vl1 = *(const uint4*)(pAl + a64 + k0);
        uint4 wh  = *(const uint4*)(pBh + k0);
        uint4 wl  = *(const uint4*)(pBl + k0);
        __syncthreads();
        *(uint4*)&sAh[ar][acl]      = vh0;
        *(uint4*)&sAh[ar + 64][acl] = vh1;
        *(uint4*)&sAl[ar][acl]      = vl0;
        *(uint4*)&sAl[ar + 64][acl] = vl1;
        *(uint4*)&sBh[ar][acl]      = wh;
        *(uint4*)&sBl[ar][acl]      = wl;
        __syncthreads();
#pragma unroll
        for (int ks = 0; ks < 2; ks++) {
            uint32_t fAh[2][4], fAl[2][4], fBh[4][2], fBl[4][2];
#pragma unroll
            for (int mt = 0; mt < 2; mt++) {
                ldm4(fAh[mt], adAh[mt] + ks*32);
                ldm4(fAl[mt], adAl[mt] + ks*32);
            }
#pragma unroll
            for (int pr = 0; pr < 2; pr++) {
                uint32_t tb[4];
                ldm4(tb, adBh[pr] + ks*32);
                fBh[2*pr][0] = tb[0]; fBh[2*pr][1]   = tb[1];
                fBh[2*pr+1][0] = tb[2]; fBh[2*pr+1][1] = tb[3];
                ldm4(tb, adBl[pr] + ks*32);
                fBl[2*pr][0] = tb[0]; fBl[2*pr][1]   = tb[1];
                fBl[2*pr+1][0] = tb[2]; fBl[2*pr+1][1] = tb[3];
            }
#pragma unroll
            for (int mt = 0; mt < 2; mt++)
#pragma unroll
                for (int nt = 0; nt < 4; nt++) {
                    mma16816(acc[mt][nt], fAh[mt], fBh[nt]);
                    mma16816(acc[mt][nt], fAh[mt], fBl[nt]);
                    mma16816(acc[mt][nt], fAl[mt], fBh[nt]);
                }
        }
    }

#pragma unroll
    for (int mt = 0; mt < 2; mt++)
#pragma unroll
        for (int nt = 0; nt < 4; nt++) {
            int r = m0 + mrow + mt*16 + (lane >> 2);
            int c = n0 + ncol + nt*8 + (lane & 3)*2;
            float* a4 = acc[mt][nt];
            if (EPI == 0) {
                float b0v = d.bias ? d.bias[c] : 0.f;
                float b1v = d.bias ? d.bias[c+1] : 0.f;
                d.C[(size_t)r*d.ldc + c]       = d.scale*(a4[0]+b0v);
                d.C[(size_t)r*d.ldc + c+1]     = d.scale*(a4[1]+b1v);
                d.C[(size_t)(r+8)*d.ldc + c]   = d.scale*(a4[2]+b0v);
                d.C[(size_t)(r+8)*d.ldc + c+1] = d.scale*(a4[3]+b1v);
            } else {
                d.C[((size_t)r*NM + c)*8 + blockIdx.z]       = 1.f/(1.f+expf(-a4[0]));
                d.C[((size_t)r*NM + c+1)*8 + blockIdx.z]     = 1.f/(1.f+expf(-a4[1]));
                d.C[((size_t)(r+8)*NM + c)*8 + blockIdx.z]   = 1.f/(1.f+expf(-a4[2]));
                d.C[((size_t)(r+8)*NM + c+1)*8 + blockIdx.z] = 1.f/(1.f+expf(-a4[3]));
            }
        }
}

// ---------------- conversion kernels ----------------------------------------
struct RMDesc { const float* a; const float* a2; bf16* hi; bf16* lo; int n4; };
struct RMParams { RMDesc d[4]; };
__global__ __launch_bounds__(256) void split_rm(RMParams p) {
    RMDesc d = p.d[blockIdx.z];
    int i = blockIdx.x * 256 + threadIdx.x;
    if (i >= d.n4) return;
    float4 x = ((const float4*)d.a)[i];
    if (d.a2) {
        float4 y = ((const float4*)d.a2)[i];
        x.x -= y.x; x.y -= y.y; x.z -= y.z; x.w -= y.w;
    }
    float v[4] = {x.x, x.y, x.z, x.w};
    __nv_bfloat162 H[2], L[2];
#pragma unroll
    for (int k = 0; k < 2; k++) {
        bf16 h0 = __float2bfloat16(v[2*k]), h1 = __float2bfloat16(v[2*k+1]);
        H[k] = __halves2bfloat162(h0, h1);
        L[k] = __halves2bfloat162(__float2bfloat16(v[2*k]   - __bfloat162float(h0)),
                                  __float2bfloat16(v[2*k+1] - __bfloat162float(h1)));
    }
    ((__nv_bfloat162*)d.hi)[i*2] = H[0]; ((__nv_bfloat162*)d.hi)[i*2+1] = H[1];
    ((__nv_bfloat162*)d.lo)[i*2] = L[0]; ((__nv_bfloat162*)d.lo)[i*2+1] = L[1];
}

struct TRDesc { const float* src; bf16* hi; bf16* lo; int K, N; };
struct TRParams { TRDesc d[7]; };
__global__ void split_tr(TRParams p) {     // out[n][k] = in[k][n]
    TRDesc d = p.d[blockIdx.z];
    int n0 = blockIdx.x * 32, k0 = blockIdx.y * 32;
    if (n0 >= d.N || k0 >= d.K) return;
    __shared__ float tl[32][33];
    int tx = threadIdx.x, ty = threadIdx.y;
#pragma unroll
    for (int r = 0; r < 4; r++)
        tl[ty + r*8][tx] = d.src[(size_t)(k0 + ty + r*8) * d.N + n0 + tx];
    __syncthreads();
#pragma unroll
    for (int r = 0; r < 4; r++) {
        int n = n0 + ty + r*8, k = k0 + tx;
        float x = tl[tx][ty + r*8];
        bf16 h = __float2bfloat16(x);
        d.hi[(size_t)n * d.K + k] = h;
        d.lo[(size_t)n * d.K + k] = __float2bfloat16(x - __bfloat162float(h));
    }
}

// ---------------- small kernels ---------------------------------------------
__global__ void b01_kernel(const float* __restrict__ bo, const float* __restrict__ W1,
                           const float* __restrict__ b1, float* __restrict__ b01) {
    int j = threadIdx.x;
    float s = b1[j];
#pragma unroll 8
    for (int k = 0; k < DM; k++) s = fmaf(bo[k], W1[(size_t)k*256 + j], s);
    b01[j] = s;
}
__global__ void b01_add_kernel(const float* __restrict__ biv,
                               const float* __restrict__ W01, float* __restrict__ b01) {
    int j = threadIdx.x;
    float s = 0.f;
#pragma unroll 8
    for (int k = 0; k < DM; k++) s = fmaf(biv[k], W01[(size_t)k*256 + j], s);
    b01[j] += s;
}
__global__ void reduce_kernel(const float* __restrict__ At, const float* __restrict__ b01,
                              float* __restrict__ Bm) {
    int m = blockIdx.x, j = threadIdx.x;
    float s = b01[j];
#pragma unroll
    for (int h = 0; h < 8; h++) s += At[(size_t)m*2048 + h*256 + j];
    Bm[(size_t)m*256 + j] = s;
}

// ---------------- fused tail (proven in R2) ---------------------------------
__global__ __launch_bounds__(256, 2) void fuse_kernel(
    const float* __restrict__ Abuf, const float* __restrict__ Bbuf,
    const float* __restrict__ wbuf, const float* __restrict__ W2,
    const float* __restrict__ b2, const float* __restrict__ W3,
    const float* __restrict__ b3, float* __restrict__ out) {

    __shared__ __align__(16) float A_s[8*256];
    __shared__ __align__(16) float B_s[256];
    __shared__ __align__(16) float w2s[64*64];
    __shared__ float b2s[64], W3s[64], b3s;

    const int m = blockIdx.x, tid = threadIdx.x;
    {
        const float4* Ag = (const float4*)(Abuf + (size_t)m*2048);
        float4* A4 = (float4*)A_s;
        A4[tid] = Ag[tid]; A4[tid + 256] = Ag[tid + 256];
        B_s[tid] = Bbuf[(size_t)m*256 + tid];
        if (tid < 64) { b2s[tid] = b2[tid]; W3s[tid] = W3[tid]; }
        if (tid == 0) b3s = b3[0];
    }
    const int n = tid;
    const float4* wp = (const float4*)(wbuf + ((size_t)n*NM + m)*8);
    float4 wA = wp[0], wB = wp[1];
    float wr[8] = {wA.x, wA.y, wA.z, wA.w, wB.x, wB.y, wB.z, wB.w};

    ull acc[32];
#pragma unroll
    for (int tt = 0; tt < 32; tt++) acc[tt] = 0ULL;

    for (int c = 0; c < 4; c++) {
        __syncthreads();
        {
            const float4* w2g = (const float4*)(W2 + c*4096);
            float4* w2s4 = (float4*)w2s;
#pragma unroll
            for (int r = 0; r < 4; r++) w2s4[tid + r*256] = w2g[tid + r*256];
        }
        __syncthreads();
        for (int jj = 0; jj < 64; jj += 4) {
            const int j = c*64 + jj;
            float4 hb = *(const float4*)&B_s[j];
            float hv[4] = {hb.x, hb.y, hb.z, hb.w};
#pragma unroll
            for (int h = 0; h < 8; h++) {
                float4 a = *(const float4*)&A_s[h*256 + j];
                hv[0] = fmaf(wr[h], a.x, hv[0]);
                hv[1] = fmaf(wr[h], a.y, hv[1]);
                hv[2] = fmaf(wr[h], a.z, hv[2]);
                hv[3] = fmaf(wr[h], a.w, hv[3]);
            }
#pragma unroll
            for (int u = 0; u < 4; u++) {
                float hj = fmaxf(hv[u], 0.f);
                ull hh; DUP2(hh, hj);
                const ulonglong2* row = (const ulonglong2*)(w2s + (jj + u)*64);
#pragma unroll
                for (int tt = 0; tt < 16; tt++) {
                    ulonglong2 pv = row[tt];
                    FMA2(acc[2*tt+0], hh, pv.x);
                    FMA2(acc[2*tt+1], hh, pv.y);
                }
            }
        }
    }
    float s = b3s;
#pragma unroll
    for (int tt = 0; tt < 32; tt++) {
        float lo, hi;
        UNPK2(lo, hi, acc[tt]);
        lo = fmaxf(lo + b2s[2*tt+0], 0.f);
        hi = fmaxf(hi + b2s[2*tt+1], 0.f);
        s = fmaf(lo, W3s[2*tt+0], s);
        s = fmaf(hi, W3s[2*tt+1], s);
    }
    out[(size_t)n*NM + m] = 0.5f * tanhf(s);
}

// ---------------- launch ----------------------------------------------------
extern "C" void kernel_launch(void* const* d_in, const int* in_sizes, int n_in,
                              void* d_out, int out_size) {
    const float* Q   = (const float*)d_in[0];
    const float* IMG = (const float*)d_in[1];
    const float* TGT = (const float*)d_in[2];
    const float* Wq  = (const float*)d_in[3];
    const float* bq  = (const float*)d_in[4];
    const float* Wi  = (const float*)d_in[5];
    const float* bi  = (const float*)d_in[6];
    const float* Wt  = (const float*)d_in[7];
    const float* bt  = (const float*)d_in[8];
    const float* Wiq = (const float*)d_in[9];
    const float* biq = (const float*)d_in[10];
    const float* Wik = (const float*)d_in[11];
    const float* Wiv = (const float*)d_in[13];
    const float* biv = (const float*)d_in[14];
    const float* Wo  = (const float*)d_in[15];
    const float* bo  = (const float*)d_in[16];
    const float* W1  = (const float*)d_in[17];
    const float* b1  = (const float*)d_in[18];
    const float* W2  = (const float*)d_in[19];
    const float* b2  = (const float*)d_in[20];
    const float* W3  = (const float*)d_in[21];
    const float* b3  = (const float*)d_in[22];
    float* out = (float*)d_out;

    float* F; bf16* B;
    cudaGetSymbolAddress((void**)&F, g_f);
    cudaGetSymbolAddress((void**)&B, g_b);
    float *q = F+F_q, *ip = F+F_ip, *tp = F+F_tp, *qh = F+F_qh, *kd = F+F_kd;
    float *vd = F+F_vd, *vt = F+F_vt, *W01 = F+F_W01, *b01 = F+F_b01;
    float *Ah = F+F_Ah, *At = F+F_At, *Bm = F+F_Bm, *wb = F+F_w;

#define HI(off) (B + (off))
#define LO(off, sz) (B + (off) + (sz))
    const float scale = 1.0f / sqrtf(96.0f);

    // C1: split row-major inputs
    RMParams rm1 = {};
    rm1.d[0] = {Q,   0, HI(B_Qs),   LO(B_Qs,   256*768), 256*768/4};
    rm1.d[1] = {IMG, 0, HI(B_IMGs), LO(B_IMGs, 512*768), 512*768/4};
    rm1.d[2] = {TGT, 0, HI(B_TGTs), LO(B_TGTs, 512*768), 512*768/4};
    rm1.d[3] = {Wo,  0, HI(B_Wos),  LO(B_Wos,  768*768), 768*768/4};
    split_rm<<<dim3(576, 1, 4), 256>>>(rm1);

    // C2: transpose+split weights (B operand = W^T, NxK)
    TRParams tr1 = {};
    tr1.d[0] = {Wq,  HI(B_WqT),  LO(B_WqT,  768*768), 768, 768};
    tr1.d[1] = {Wi,  HI(B_WiT),  LO(B_WiT,  768*768), 768, 768};
    tr1.d[2] = {Wt,  HI(B_WtT),  LO(B_WtT,  768*768), 768, 768};
    tr1.d[3] = {Wiq, HI(B_WiqT), LO(B_WiqT, 768*768), 768, 768};
    tr1.d[4] = {Wik, HI(B_WikT), LO(B_WikT, 768*768), 768, 768};
    tr1.d[5] = {Wiv, HI(B_WivT), LO(B_WivT, 768*768), 768, 768};
    tr1.d[6] = {W1,  HI(B_W1T),  LO(B_W1T,  256*768), 768, 256};
    split_tr<<<dim3(24, 24, 7), dim3(32, 8)>>>(tr1);

    // L1: stage-1 projections + W01 = Wo@W1
    TCParams p1 = {};
    p1.d[0] = {HI(B_Qs),   LO(B_Qs,  256*768), HI(B_WqT), LO(B_WqT, 768*768), bq, q,   768, 768, 768, 256, 768, 768, 1.f};
    p1.d[1] = {HI(B_IMGs), LO(B_IMGs,512*768), HI(B_WiT), LO(B_WiT, 768*768), bi, ip,  768, 768, 768, 512, 768, 768, 1.f};
    p1.d[2] = {HI(B_TGTs), LO(B_TGTs,512*768), HI(B_WtT), LO(B_WtT, 768*768), bt, tp,  768, 768, 768, 512, 768, 768, 1.f};
    p1.d[3] = {HI(B_Wos),  LO(B_Wos, 768*768), HI(B_W1T), LO(B_W1T, 256*768), 0,  W01, 768, 768, 256, 768, 256, 768, 1.f};
    mma_gemm<0><<<dim3(12, 6, 4), 256>>>(p1);

    b01_kernel<<<1, 256>>>(bo, W1, b1, b01);
    b01_add_kernel<<<1, 256>>>(biv, W01, b01);

    // C3: split stage-1 activations (q, ip-tp, tp)
    RMParams rm2 = {};
    rm2.d[0] = {q,  0,  HI(B_qs),  LO(B_qs,  256*768), 256*768/4};
    rm2.d[1] = {ip, tp, HI(B_dps), LO(B_dps, 512*768), 512*768/4};
    rm2.d[2] = {tp, 0,  HI(B_tps), LO(B_tps, 512*768), 512*768/4};
    split_rm<<<dim3(384, 1, 3), 256>>>(rm2);

    // L2: qh, kd, vd, vt
    TCParams p2 = {};
    p2.d[0] = {HI(B_qs),  LO(B_qs, 256*768), HI(B_WiqT), LO(B_WiqT, 768*768), biq, qh, 768, 768, 768, 256, 768, 768, scale};
    p2.d[1] = {HI(B_dps), LO(B_dps,512*768), HI(B_WikT), LO(B_WikT, 768*768), 0,   kd, 768, 768, 768, 512, 768, 768, 1.f};
    p2.d[2] = {HI(B_dps), LO(B_dps,512*768), HI(B_WivT), LO(B_WivT, 768*768), 0,   vd, 768, 768, 768, 512, 768, 768, 1.f};
    p2.d[3] = {HI(B_tps), LO(B_tps,512*768), HI(B_WivT), LO(B_WivT, 768*768), 0,   vt, 768, 768, 768, 512, 768, 768, 1.f};
    mma_gemm<0><<<dim3(12, 4, 4), 256>>>(p2);

    // C4: split stage-2 activations + W01^T
    RMParams rm3 = {};
    rm3.d[0] = {qh, 0, HI(B_qhs), LO(B_qhs, 256*768), 256*768/4};
    rm3.d[1] = {kd, 0, HI(B_kds), LO(B_kds, 512*768), 512*768/4};
    rm3.d[2] = {vd, 0, HI(B_vds), LO(B_vds, 512*768), 512*768/4};
    rm3.d[3] = {vt, 0, HI(B_vts), LO(B_vts, 512*768), 512*768/4};
    split_rm<<<dim3(384, 1, 4), 256>>>(rm3);
    TRParams tr2 = {};
    tr2.d[0] = {W01, HI(B_W01T), LO(B_W01T, 256*768), 768, 256};
    split_tr<<<dim3(8, 24, 1), dim3(32, 8)>>>(tr2);

    // L4: attention weights (per-head K=96, sigmoid epilogue scatter)
    TCParams pl = {};
    pl.d[0] = {HI(B_qhs), LO(B_qhs, 256*768), HI(B_kds), LO(B_kds, 512*768), 0, wb,
               768, 768, 0, 256, 512, 96, 1.f};
    mma_gemm<1><<<dim3(8, 2, 8), 256>>>(pl);

    // L3: per-head Ah/At = vd_h/vt_h @ W01_h  (K=96)
    TCParams p3 = {};
    for (int h = 0; h < 8; h++) {
        p3.d[h]   = {HI(B_vds) + h*96, LO(B_vds, 512*768) + h*96,
                     HI(B_W01T) + h*96, LO(B_W01T, 256*768) + h*96, 0,
                     Ah + h*256, 768, 768, 2048, 512, 256, 96, 1.f};
        p3.d[8+h] = {HI(B_vts) + h*96, LO(B_vts, 512*768) + h*96,
                     HI(B_W01T) + h*96, LO(B_W01T, 256*768) + h*96, 0,
                     At + h*256, 768, 768, 2048, 512, 256, 96, 1.f};
    }
    mma_gemm<0><<<dim3(4, 4, 16), 256>>>(p3);

    reduce_kernel<<<NM, 256>>>(At, b01, Bm);
    fuse_kernel<<<NM, 256>>>(Ah, Bm, wb, W2, b2, W3, b3, out);
}

// round 6
// speedup vs baseline: 1.4355x; 1.1414x over previous
#include <cuda_runtime.h>
#include <cuda_bf16.h>
#include <cstdint>
#include <cmath>

typedef unsigned long long ull;
typedef __nv_bfloat16 bf16;
#define DM 768
#define NQ 256
#define NM 512

#define FMA2(acc, a, b) asm("fma.rn.f32x2 %0, %1, %2, %0;" : "+l"(acc) : "l"(a), "l"(b))
#define DUP2(d, s)      asm("mov.b64 %0, {%1, %1};" : "=l"(d) : "f"(s))
#define UNPK2(lo, hi, s) asm("mov.b64 {%0, %1}, %2;" : "=f"(lo), "=f"(hi) : "l"(s))

__device__ __forceinline__ uint32_t smem_u32(const void* p) {
    uint32_t a;
    asm("{ .reg .u64 t; cvta.to.shared.u64 t, %1; cvt.u32.u64 %0, t; }" : "=r"(a) : "l"(p));
    return a;
}
__device__ __forceinline__ void ldm4(uint32_t* r, uint32_t addr) {
    asm volatile("ldmatrix.sync.aligned.m8n8.x4.shared.b16 {%0,%1,%2,%3}, [%4];"
        : "=r"(r[0]), "=r"(r[1]), "=r"(r[2]), "=r"(r[3]) : "r"(addr));
}
__device__ __forceinline__ void mma16816(float* c, const uint32_t* a, const uint32_t* b) {
    asm volatile("mma.sync.aligned.m16n8k16.row.col.f32.bf16.bf16.f32 "
        "{%0,%1,%2,%3}, {%4,%5,%6,%7}, {%8,%9}, {%0,%1,%2,%3};"
        : "+f"(c[0]), "+f"(c[1]), "+f"(c[2]), "+f"(c[3])
        : "r"(a[0]), "r"(a[1]), "r"(a[2]), "r"(a[3]), "r"(b[0]), "r"(b[1]));
}

// ---------------- scratch ---------------------------------------------------
constexpr size_t F_q    = 0;
constexpr size_t F_ip   = F_q    + 256*768;
constexpr size_t F_tp   = F_ip   + 512*768;
constexpr size_t F_W01  = F_tp   + 512*768;
constexpr size_t F_b01  = F_W01  + 768*256;
constexpr size_t F_part = F_b01  + 256;
constexpr size_t F_Ah   = F_part + 48*256;
constexpr size_t F_At   = F_Ah   + 512*2048;
constexpr size_t F_Bm   = F_At   + 512*2048;
constexpr size_t F_w    = F_Bm   + 512*256;
constexpr size_t F_END  = F_w    + 256*512*8;
__device__ __align__(16) float g_f[F_END];

constexpr size_t B_Qs   = 0;
constexpr size_t B_IMGs = B_Qs   + 2*256*768;
constexpr size_t B_TGTs = B_IMGs + 2*512*768;
constexpr size_t B_Wos  = B_TGTs + 2*512*768;
constexpr size_t B_WqT  = B_Wos  + 2*768*768;
constexpr size_t B_WiT  = B_WqT  + 2*768*768;
constexpr size_t B_WtT  = B_WiT  + 2*768*768;
constexpr size_t B_WiqT = B_WtT  + 2*768*768;
constexpr size_t B_WikT = B_WiqT + 2*768*768;
constexpr size_t B_WivT = B_WikT + 2*768*768;
constexpr size_t B_W1T  = B_WivT + 2*768*768;
constexpr size_t B_qs   = B_W1T  + 2*256*768;
constexpr size_t B_dps  = B_qs   + 2*256*768;
constexpr size_t B_tps  = B_dps  + 2*512*768;
constexpr size_t B_qhs  = B_tps  + 2*512*768;
constexpr size_t B_kds  = B_qhs  + 2*256*768;
constexpr size_t B_vds  = B_kds  + 2*512*768;
constexpr size_t B_vts  = B_vds  + 2*512*768;
constexpr size_t B_W01T = B_vts  + 2*512*768;
constexpr size_t B_END  = B_W01T + 2*256*768;
__device__ __align__(16) bf16 g_b[B_END];

// ---------------- bf16-split MMA GEMM ---------------------------------------
struct TCDesc {
    const bf16 *Ah, *Al, *Bh, *Bl;
    const float* bias;
    float* C;
    bf16 *Chi, *Clo;
    int lda, ldb, ldc, M, N, K;
    float scale;
    int mode;                 // 0 = fp32 C, 2 = bf16 hi/lo split
};
struct TCParams { TCDesc d[16]; };

template<int EPI>
__global__ __launch_bounds__(256) void mma_gemm(TCParams p) {
    TCDesc d = p.d[EPI ? 0 : blockIdx.z];
    const int m0 = blockIdx.y * 128, n0 = blockIdx.x * 64;
    if (m0 >= d.M || n0 >= d.N) return;
    const int hof = EPI ? blockIdx.z * 96 : 0;

    __shared__ __align__(16) bf16 sAh[128][40], sAl[128][40], sBh[64][40], sBl[64][40];

    const int t = threadIdx.x, lane = t & 31, w = t >> 5;
    const int mrow = (w & 3) * 32, ncol = (w >> 2) * 32;

    const int ar = t >> 2, acl = (t & 3) * 8;
    const bf16* pAh = d.Ah + hof + (size_t)(m0 + ar) * d.lda + acl;
    const bf16* pAl = d.Al + hof + (size_t)(m0 + ar) * d.lda + acl;
    const bf16* pBh = d.Bh + hof + (size_t)(n0 + ar) * d.ldb + acl;
    const bf16* pBl = d.Bl + hof + (size_t)(n0 + ar) * d.ldb + acl;
    const size_t a64 = (size_t)64 * d.lda;

    const uint32_t uAh = smem_u32(&sAh[0][0]), uAl = smem_u32(&sAl[0][0]);
    const uint32_t uBh = smem_u32(&sBh[0][0]), uBl = smem_u32(&sBl[0][0]);
    const int aR = mrow + (lane & 15), aC = (lane >> 4) * 8;
    const int bR = ncol + (lane & 7) + ((lane & 16) >> 1), bC = lane & 8;
    uint32_t adAh[2], adAl[2], adBh[2], adBl[2];
#pragma unroll
    for (int mt = 0; mt < 2; mt++) {
        adAh[mt] = uAh + ((aR + mt*16)*40 + aC)*2;
        adAl[mt] = uAl + ((aR + mt*16)*40 + aC)*2;
    }
#pragma unroll
    for (int pr = 0; pr < 2; pr++) {
        adBh[pr] = uBh + ((bR + pr*16)*40 + bC)*2;
        adBl[pr] = uBl + ((bR + pr*16)*40 + bC)*2;
    }

    float acc[2][4][4];
#pragma unroll
    for (int mt = 0; mt < 2; mt++)
#pragma unroll
        for (int nt = 0; nt < 4; nt++)
#pragma unroll
            for (int i = 0; i < 4; i++) acc[mt][nt][i] = 0.f;

    const int nkt = d.K >> 5;
    for (int kt = 0; kt < nkt; kt++) {
        const int k0 = kt * 32;
        uint4 vh0 = *(const uint4*)(pAh + k0);
        uint4 vh1 = *(const uint4*)(pAh + a64 + k0);
        uint4 vl0 = *(const uint4*)(pAl + k0);
        uint4 vl1 = *(const uint4*)(pAl + a64 + k0);
        uint4 wh  = *(const uint4*)(pBh + k0);
        uint4 wl  = *(const uint4*)(pBl + k0);
        __syncthreads();
        *(uint4*)&sAh[ar][acl]      = vh0;
        *(uint4*)&sAh[ar + 64][acl] = vh1;
        *(uint4*)&sAl[ar][acl]      = vl0;
        *(uint4*)&sAl[ar + 64][acl] = vl1;
        *(uint4*)&sBh[ar][acl]      = wh;
        *(uint4*)&sBl[ar][acl]      = wl;
        __syncthreads();
#pragma unroll
        for (int ks = 0; ks < 2; ks++) {
            uint32_t fAh[2][4], fAl[2][4], fBh[4][2], fBl[4][2];
#pragma unroll
            for (int mt = 0; mt < 2; mt++) {
                ldm4(fAh[mt], adAh[mt] + ks*32);
                ldm4(fAl[mt], adAl[mt] + ks*32);
            }
#pragma unroll
            for (int pr = 0; pr < 2; pr++) {
                uint32_t tb[4];
                ldm4(tb, adBh[pr] + ks*32);
                fBh[2*pr][0] = tb[0]; fBh[2*pr][1]   = tb[1];
                fBh[2*pr+1][0] = tb[2]; fBh[2*pr+1][1] = tb[3];
                ldm4(tb, adBl[pr] + ks*32);
                fBl[2*pr][0] = tb[0]; fBl[2*pr][1]   = tb[1];
                fBl[2*pr+1][0] = tb[2]; fBl[2*pr+1][1] = tb[3];
            }
#pragma unroll
            for (int mt = 0; mt < 2; mt++)
#pragma unroll
                for (int nt = 0; nt < 4; nt++) {
                    mma16816(acc[mt][nt], fAh[mt], fBh[nt]);
                    mma16816(acc[mt][nt], fAh[mt], fBl[nt]);
                    mma16816(acc[mt][nt], fAl[mt], fBh[nt]);
                }
        }
    }

#pragma unroll
    for (int mt = 0; mt < 2; mt++)
#pragma unroll
        for (int nt = 0; nt < 4; nt++) {
            int r = m0 + mrow + mt*16 + (lane >> 2);
            int c = n0 + ncol + nt*8 + (lane & 3)*2;
            float* a4 = acc[mt][nt];
            if (EPI == 1) {
                d.C[((size_t)r*NM + c)*8 + blockIdx.z]       = 1.f/(1.f+expf(-a4[0]));
                d.C[((size_t)r*NM + c+1)*8 + blockIdx.z]     = 1.f/(1.f+expf(-a4[1]));
                d.C[((size_t)(r+8)*NM + c)*8 + blockIdx.z]   = 1.f/(1.f+expf(-a4[2]));
                d.C[((size_t)(r+8)*NM + c+1)*8 + blockIdx.z] = 1.f/(1.f+expf(-a4[3]));
            } else {
                float b0v = d.bias ? d.bias[c] : 0.f;
                float b1v = d.bias ? d.bias[c+1] : 0.f;
                float v00 = d.scale*(a4[0]+b0v), v01 = d.scale*(a4[1]+b1v);
                float v10 = d.scale*(a4[2]+b0v), v11 = d.scale*(a4[3]+b1v);
                if (d.mode == 0) {
                    d.C[(size_t)r*d.ldc + c]       = v00;
                    d.C[(size_t)r*d.ldc + c+1]     = v01;
                    d.C[(size_t)(r+8)*d.ldc + c]   = v10;
                    d.C[(size_t)(r+8)*d.ldc + c+1] = v11;
                } else {
                    float vv[4] = {v00, v01, v10, v11};
                    size_t ix[4] = {(size_t)r*d.ldc + c, (size_t)r*d.ldc + c+1,
                                    (size_t)(r+8)*d.ldc + c, (size_t)(r+8)*d.ldc + c+1};
#pragma unroll
                    for (int u = 0; u < 4; u++) {
                        bf16 hh = __float2bfloat16(vv[u]);
                        d.Chi[ix[u]] = hh;
                        d.Clo[ix[u]] = __float2bfloat16(vv[u] - __bfloat162float(hh));
                    }
                }
            }
        }
}

// ---------------- conversion kernels ----------------------------------------
struct RMDesc { const float* a; const float* a2; bf16* hi; bf16* lo; int n4; };
struct RMParams { RMDesc d[4]; };
__global__ __launch_bounds__(256) void split_rm(RMParams p) {
    RMDesc d = p.d[blockIdx.z];
    int i = blockIdx.x * 256 + threadIdx.x;
    if (i >= d.n4) return;
    float4 x = ((const float4*)d.a)[i];
    if (d.a2) {
        float4 y = ((const float4*)d.a2)[i];
        x.x -= y.x; x.y -= y.y; x.z -= y.z; x.w -= y.w;
    }
    float v[4] = {x.x, x.y, x.z, x.w};
    __nv_bfloat162 H[2], L[2];
#pragma unroll
    for (int k = 0; k < 2; k++) {
        bf16 h0 = __float2bfloat16(v[2*k]), h1 = __float2bfloat16(v[2*k+1]);
        H[k] = __halves2bfloat162(h0, h1);
        L[k] = __halves2bfloat162(__float2bfloat16(v[2*k]   - __bfloat162float(h0)),
                                  __float2bfloat16(v[2*k+1] - __bfloat162float(h1)));
    }
    ((__nv_bfloat162*)d.hi)[i*2] = H[0]; ((__nv_bfloat162*)d.hi)[i*2+1] = H[1];
    ((__nv_bfloat162*)d.lo)[i*2] = L[0]; ((__nv_bfloat162*)d.lo)[i*2+1] = L[1];
}

struct TRDesc { const float* src; bf16* hi; bf16* lo; int K, N; };
struct TRParams { TRDesc d[7]; };
__global__ void split_tr(TRParams p) {
    TRDesc d = p.d[blockIdx.z];
    int n0 = blockIdx.x * 32, k0 = blockIdx.y * 32;
    if (n0 >= d.N || k0 >= d.K) return;
    __shared__ float tl[32][33];
    int tx = threadIdx.x, ty = threadIdx.y;
#pragma unroll
    for (int r = 0; r < 4; r++)
        tl[ty + r*8][tx] = d.src[(size_t)(k0 + ty + r*8) * d.N + n0 + tx];
    __syncthreads();
#pragma unroll
    for (int r = 0; r < 4; r++) {
        int n = n0 + ty + r*8, k = k0 + tx;
        float x = tl[tx][ty + r*8];
        bf16 h = __float2bfloat16(x);
        d.hi[(size_t)n * d.K + k] = h;
        d.lo[(size_t)n * d.K + k] = __float2bfloat16(x - __bfloat162float(h));
    }
}

// ---------------- parallel b01: b01 = b1 + bo@W1 + biv@W01 ------------------
__global__ void b01_part(const float* __restrict__ bo, const float* __restrict__ W1,
                         const float* __restrict__ biv, const float* __restrict__ W01,
                         float* __restrict__ part) {
    int b = blockIdx.x;                       // 48 blocks
    int kc = (b % 24) * 32;
    const float* vec = (b < 24) ? bo  : biv;
    const float* Wm  = (b < 24) ? W1  : W01;
    int j = threadIdx.x;
    float s = 0.f;
#pragma unroll
    for (int k = 0; k < 32; k++)
        s = fmaf(vec[kc + k], Wm[(size_t)(kc + k)*256 + j], s);
    part[b*256 + j] = s;
}
__global__ void b01_final(const float* __restrict__ part, const float* __restrict__ b1,
                          float* __restrict__ b01) {
    int j = threadIdx.x;
    float s = b1[j];
#pragma unroll
    for (int i = 0; i < 48; i++) s += part[i*256 + j];
    b01[j] = s;
}

__global__ void reduce_kernel(const float* __restrict__ At, const float* __restrict__ b01,
                              float* __restrict__ Bm) {
    int m = blockIdx.x, j = threadIdx.x;
    float s = b01[j];
#pragma unroll
    for (int h = 0; h < 8; h++) s += At[(size_t)m*2048 + h*256 + j];
    Bm[(size_t)m*256 + j] = s;
}

// ---------------- fused tail -------------------------------------------------
__global__ __launch_bounds__(256, 2) void fuse_kernel(
    const float* __restrict__ Abuf, const float* __restrict__ Bbuf,
    const float* __restrict__ wbuf, const float* __restrict__ W2,
    const float* __restrict__ b2, const float* __restrict__ W3,
    const float* __restrict__ b3, float* __restrict__ out) {

    __shared__ __align__(16) float A_s[8*256];
    __shared__ __align__(16) float B_s[256];
    __shared__ __align__(16) float w2s[64*64];
    __shared__ float b2s[64], W3s[64], b3s;

    const int m = blockIdx.x, tid = threadIdx.x;
    {
        const float4* Ag = (const float4*)(Abuf + (size_t)m*2048);
        float4* A4 = (float4*)A_s;
        A4[tid] = Ag[tid]; A4[tid + 256] = Ag[tid + 256];
        B_s[tid] = Bbuf[(size_t)m*256 + tid];
        if (tid < 64) { b2s[tid] = b2[tid]; W3s[tid] = W3[tid]; }
        if (tid == 0) b3s = b3[0];
    }
    const int n = tid;
    const float4* wp = (const float4*)(wbuf + ((size_t)n*NM + m)*8);
    float4 wA = wp[0], wB = wp[1];
    float wr[8] = {wA.x, wA.y, wA.z, wA.w, wB.x, wB.y, wB.z, wB.w};

    ull acc[32];
#pragma unroll
    for (int tt = 0; tt < 32; tt++) acc[tt] = 0ULL;

    for (int c = 0; c < 4; c++) {
        __syncthreads();
        {
            const float4* w2g = (const float4*)(W2 + c*4096);
            float4* w2s4 = (float4*)w2s;
#pragma unroll
            for (int r = 0; r < 4; r++) w2s4[tid + r*256] = w2g[tid + r*256];
        }
        __syncthreads();
        for (int jj = 0; jj < 64; jj += 4) {
            const int j = c*64 + jj;
            float4 hb = *(const float4*)&B_s[j];
            float hv[4] = {hb.x, hb.y, hb.z, hb.w};
#pragma unroll
            for (int h = 0; h < 8; h++) {
                float4 a = *(const float4*)&A_s[h*256 + j];
                hv[0] = fmaf(wr[h], a.x, hv[0]);
                hv[1] = fmaf(wr[h], a.y, hv[1]);
                hv[2] = fmaf(wr[h], a.z, hv[2]);
                hv[3] = fmaf(wr[h], a.w, hv[3]);
            }
#pragma unroll
            for (int u = 0; u < 4; u++) {
                float hj = fmaxf(hv[u], 0.f);
                ull hh; DUP2(hh, hj);
                const ulonglong2* row = (const ulonglong2*)(w2s + (jj + u)*64);
#pragma unroll
                for (int tt = 0; tt < 16; tt++) {
                    ulonglong2 pv = row[tt];
                    FMA2(acc[2*tt+0], hh, pv.x);
                    FMA2(acc[2*tt+1], hh, pv.y);
                }
            }
        }
    }
    float s = b3s;
#pragma unroll
    for (int tt = 0; tt < 32; tt++) {
        float lo, hi;
        UNPK2(lo, hi, acc[tt]);
        lo = fmaxf(lo + b2s[2*tt+0], 0.f);
        hi = fmaxf(hi + b2s[2*tt+1], 0.f);
        s = fmaf(lo, W3s[2*tt+0], s);
        s = fmaf(hi, W3s[2*tt+1], s);
    }
    out[(size_t)n*NM + m] = 0.5f * tanhf(s);
}

// ---------------- launch ----------------------------------------------------
extern "C" void kernel_launch(void* const* d_in, const int* in_sizes, int n_in,
                              void* d_out, int out_size) {
    const float* Q   = (const float*)d_in[0];
    const float* IMG = (const float*)d_in[1];
    const float* TGT = (const float*)d_in[2];
    const float* Wq  = (const float*)d_in[3];
    const float* bq  = (const float*)d_in[4];
    const float* Wi  = (const float*)d_in[5];
    const float* bi  = (const float*)d_in[6];
    const float* Wt  = (const float*)d_in[7];
    const float* bt  = (const float*)d_in[8];
    const float* Wiq = (const float*)d_in[9];
    const float* biq = (const float*)d_in[10];
    const float* Wik = (const float*)d_in[11];
    const float* Wiv = (const float*)d_in[13];
    const float* biv = (const float*)d_in[14];
    const float* Wo  = (const float*)d_in[15];
    const float* bo  = (const float*)d_in[16];
    const float* W1  = (const float*)d_in[17];
    const float* b1  = (const float*)d_in[18];
    const float* W2  = (const float*)d_in[19];
    const float* b2  = (const float*)d_in[20];
    const float* W3  = (const float*)d_in[21];
    const float* b3  = (const float*)d_in[22];
    float* out = (float*)d_out;

    float* F; bf16* B;
    cudaGetSymbolAddress((void**)&F, g_f);
    cudaGetSymbolAddress((void**)&B, g_b);
    float *q = F+F_q, *ip = F+F_ip, *tp = F+F_tp;
    float *W01 = F+F_W01, *b01 = F+F_b01, *part = F+F_part;
    float *Ah = F+F_Ah, *At = F+F_At, *Bm = F+F_Bm, *wb = F+F_w;
    (void)q;

#define HI(off) (B + (off))
#define LO(off, sz) (B + (off) + (sz))
    const float scale = 1.0f / sqrtf(96.0f);

    // C1: split row-major inputs
    RMParams rm1 = {};
    rm1.d[0] = {Q,   0, HI(B_Qs),   LO(B_Qs,   256*768), 256*768/4};
    rm1.d[1] = {IMG, 0, HI(B_IMGs), LO(B_IMGs, 512*768), 512*768/4};
    rm1.d[2] = {TGT, 0, HI(B_TGTs), LO(B_TGTs, 512*768), 512*768/4};
    rm1.d[3] = {Wo,  0, HI(B_Wos),  LO(B_Wos,  768*768), 768*768/4};
    split_rm<<<dim3(576, 1, 4), 256>>>(rm1);

    // C2: transpose+split weights
    TRParams tr1 = {};
    tr1.d[0] = {Wq,  HI(B_WqT),  LO(B_WqT,  768*768), 768, 768};
    tr1.d[1] = {Wi,  HI(B_WiT),  LO(B_WiT,  768*768), 768, 768};
    tr1.d[2] = {Wt,  HI(B_WtT),  LO(B_WtT,  768*768), 768, 768};
    tr1.d[3] = {Wiq, HI(B_WiqT), LO(B_WiqT, 768*768), 768, 768};
    tr1.d[4] = {Wik, HI(B_WikT), LO(B_WikT, 768*768), 768, 768};
    tr1.d[5] = {Wiv, HI(B_WivT), LO(B_WivT, 768*768), 768, 768};
    tr1.d[6] = {W1,  HI(B_W1T),  LO(B_W1T,  256*768), 768, 256};
    split_tr<<<dim3(24, 24, 7), dim3(32, 8)>>>(tr1);

    // L1: stage-1 projections (q split-direct) + W01 = Wo@W1
    TCParams p1 = {};
    p1.d[0] = {HI(B_Qs),   LO(B_Qs,  256*768), HI(B_WqT), LO(B_WqT, 768*768), bq, 0,
               HI(B_qs), LO(B_qs, 256*768), 768, 768, 768, 256, 768, 768, 1.f, 2};
    p1.d[1] = {HI(B_IMGs), LO(B_IMGs,512*768), HI(B_WiT), LO(B_WiT, 768*768), bi, ip,
               0, 0, 768, 768, 768, 512, 768, 768, 1.f, 0};
    p1.d[2] = {HI(B_TGTs), LO(B_TGTs,512*768), HI(B_WtT), LO(B_WtT, 768*768), bt, tp,
               0, 0, 768, 768, 768, 512, 768, 768, 1.f, 0};
    p1.d[3] = {HI(B_Wos),  LO(B_Wos, 768*768), HI(B_W1T), LO(B_W1T, 256*768), 0, W01,
               0, 0, 768, 768, 256, 768, 256, 768, 1.f, 0};
    mma_gemm<0><<<dim3(12, 6, 4), 256>>>(p1);

    // parallel b01 = b1 + bo@W1 + biv@W01   (needs W01 -> after L1)
    b01_part<<<48, 256>>>(bo, W1, biv, W01, part);
    b01_final<<<1, 256>>>(part, b1, b01);

    // C3: split stage-1 activations (ip-tp diff, tp)
    RMParams rm2 = {};
    rm2.d[0] = {ip, tp, HI(B_dps), LO(B_dps, 512*768), 512*768/4};
    rm2.d[1] = {tp, 0,  HI(B_tps), LO(B_tps, 512*768), 512*768/4};
    split_rm<<<dim3(384, 1, 2), 256>>>(rm2);

    // C2b: W01^T split (needs W01)
    TRParams tr2 = {};
    tr2.d[0] = {W01, HI(B_W01T), LO(B_W01T, 256*768), 768, 256};
    split_tr<<<dim3(8, 24, 1), dim3(32, 8)>>>(tr2);

    // L2: qh, kd, vd, vt — all written directly as bf16 splits
    TCParams p2 = {};
    p2.d[0] = {HI(B_qs),  LO(B_qs, 256*768), HI(B_WiqT), LO(B_WiqT, 768*768), biq, 0,
               HI(B_qhs), LO(B_qhs, 256*768), 768, 768, 768, 256, 768, 768, scale, 2};
    p2.d[1] = {HI(B_dps), LO(B_dps,512*768), HI(B_WikT), LO(B_WikT, 768*768), 0, 0,
               HI(B_kds), LO(B_kds, 512*768), 768, 768, 768, 512, 768, 768, 1.f, 2};
    p2.d[2] = {HI(B_dps), LO(B_dps,512*768), HI(B_WivT), LO(B_WivT, 768*768), 0, 0,
               HI(B_vds), LO(B_vds, 512*768), 768, 768, 768, 512, 768, 768, 1.f, 2};
    p2.d[3] = {HI(B_tps), LO(B_tps,512*768), HI(B_WivT), LO(B_WivT, 768*768), 0, 0,
               HI(B_vts), LO(B_vts, 512*768), 768, 768, 768, 512, 768, 768, 1.f, 2};
    mma_gemm<0><<<dim3(12, 4, 4), 256>>>(p2);

    // L4: attention weights (per-head K=96, sigmoid epilogue scatter)
    TCParams pl = {};
    pl.d[0] = {HI(B_qhs), LO(B_qhs, 256*768), HI(B_kds), LO(B_kds, 512*768), 0, wb,
               0, 0, 768, 768, 0, 256, 512, 96, 1.f, 0};
    mma_gemm<1><<<dim3(8, 2, 8), 256>>>(pl);

    // L3: per-head Ah/At = vd_h/vt_h @ W01_h  (K=96)
    TCParams p3 = {};
    for (int h = 0; h < 8; h++) {
        p3.d[h]   = {HI(B_vds) + h*96, LO(B_vds, 512*768) + h*96,
                     HI(B_W01T) + h*96, LO(B_W01T, 256*768) + h*96, 0,
                     Ah + h*256, 0, 0, 768, 768, 2048, 512, 256, 96, 1.f, 0};
        p3.d[8+h] = {HI(B_vts) + h*96, LO(B_vts, 512*768) + h*96,
                     HI(B_W01T) + h*96, LO(B_W01T, 256*768) + h*96, 0,
                     At + h*256, 0, 0, 768, 768, 2048, 512, 256, 96, 1.f, 0};
    }
    mma_gemm<0><<<dim3(4, 4, 16), 256>>>(p3);

    reduce_kernel<<<NM, 256>>>(At, b01, Bm);
    fuse_kernel<<<NM, 256>>>(Ah, Bm, wb, W2, b2, W3, b3, out);
}

// round 7
// speedup vs baseline: 2.4456x; 1.7037x over previous
#include <cuda_runtime.h>
#include <cuda_bf16.h>
#include <cstdint>
#include <cmath>

typedef unsigned long long ull;
typedef __nv_bfloat16 bf16;
#define DM 768
#define NQ 256
#define NM 512

#define FMA2(acc, a, b) asm("fma.rn.f32x2 %0, %1, %2, %0;" : "+l"(acc) : "l"(a), "l"(b))
#define DUP2(d, s)      asm("mov.b64 %0, {%1, %1};" : "=l"(d) : "f"(s))
#define UNPK2(lo, hi, s) asm("mov.b64 {%0, %1}, %2;" : "=f"(lo), "=f"(hi) : "l"(s))

__device__ __forceinline__ uint32_t smem_u32(const void* p) {
    uint32_t a;
    asm("{ .reg .u64 t; cvta.to.shared.u64 t, %1; cvt.u32.u64 %0, t; }" : "=r"(a) : "l"(p));
    return a;
}
__device__ __forceinline__ void ldm4(uint32_t* r, uint32_t addr) {
    asm volatile("ldmatrix.sync.aligned.m8n8.x4.shared.b16 {%0,%1,%2,%3}, [%4];"
        : "=r"(r[0]), "=r"(r[1]), "=r"(r[2]), "=r"(r[3]) : "r"(addr));
}
__device__ __forceinline__ void mma16816(float* c, const uint32_t* a, const uint32_t* b) {
    asm volatile("mma.sync.aligned.m16n8k16.row.col.f32.bf16.bf16.f32 "
        "{%0,%1,%2,%3}, {%4,%5,%6,%7}, {%8,%9}, {%0,%1,%2,%3};"
        : "+f"(c[0]), "+f"(c[1]), "+f"(c[2]), "+f"(c[3])
        : "r"(a[0]), "r"(a[1]), "r"(a[2]), "r"(a[3]), "r"(b[0]), "r"(b[1]));
}

// ---------------- scratch ---------------------------------------------------
constexpr size_t F_q    = 0;
constexpr size_t F_ip   = F_q    + 256*768;
constexpr size_t F_tp   = F_ip   + 512*768;
constexpr size_t F_W01  = F_tp   + 512*768;
constexpr size_t F_b01  = F_W01  + 768*256;
constexpr size_t F_part = F_b01  + 256;
constexpr size_t F_Ah   = F_part + 48*256;
constexpr size_t F_At   = F_Ah   + 512*2048;
constexpr size_t F_Bm   = F_At   + 512*2048;
constexpr size_t F_w    = F_Bm   + 512*256;
constexpr size_t F_END  = F_w    + 256*512*8;
__device__ __align__(16) float g_f[F_END];

constexpr size_t B_Qs   = 0;
constexpr size_t B_IMGs = B_Qs   + 2*256*768;
constexpr size_t B_TGTs = B_IMGs + 2*512*768;
constexpr size_t B_Wos  = B_TGTs + 2*512*768;
constexpr size_t B_WqT  = B_Wos  + 2*768*768;
constexpr size_t B_WiT  = B_WqT  + 2*768*768;
constexpr size_t B_WtT  = B_WiT  + 2*768*768;
constexpr size_t B_WiqT = B_WtT  + 2*768*768;
constexpr size_t B_WikT = B_WiqT + 2*768*768;
constexpr size_t B_WivT = B_WikT + 2*768*768;
constexpr size_t B_W1T  = B_WivT + 2*768*768;
constexpr size_t B_W2T  = B_W1T  + 2*256*768;
constexpr size_t B_qs   = B_W2T  + 2*64*256;
constexpr size_t B_dps  = B_qs   + 2*256*768;
constexpr size_t B_tps  = B_dps  + 2*512*768;
constexpr size_t B_qhs  = B_tps  + 2*512*768;
constexpr size_t B_kds  = B_qhs  + 2*256*768;
constexpr size_t B_vds  = B_kds  + 2*512*768;
constexpr size_t B_vts  = B_vds  + 2*512*768;
constexpr size_t B_W01T = B_vts  + 2*512*768;
constexpr size_t B_END  = B_W01T + 2*256*768;
__device__ __align__(16) bf16 g_b[B_END];

// ---------------- bf16-split MMA GEMM (proven R5/R6) ------------------------
struct TCDesc {
    const bf16 *Ah, *Al, *Bh, *Bl;
    const float* bias;
    float* C;
    bf16 *Chi, *Clo;
    int lda, ldb, ldc, M, N, K;
    float scale;
    int mode;
};
struct TCParams { TCDesc d[16]; };

template<int EPI>
__global__ __launch_bounds__(256) void mma_gemm(TCParams p) {
    TCDesc d = p.d[EPI ? 0 : blockIdx.z];
    const int m0 = blockIdx.y * 128, n0 = blockIdx.x * 64;
    if (m0 >= d.M || n0 >= d.N) return;
    const int hof = EPI ? blockIdx.z * 96 : 0;

    __shared__ __align__(16) bf16 sAh[128][40], sAl[128][40], sBh[64][40], sBl[64][40];

    const int t = threadIdx.x, lane = t & 31, w = t >> 5;
    const int mrow = (w & 3) * 32, ncol = (w >> 2) * 32;

    const int ar = t >> 2, acl = (t & 3) * 8;
    const bf16* pAh = d.Ah + hof + (size_t)(m0 + ar) * d.lda + acl;
    const bf16* pAl = d.Al + hof + (size_t)(m0 + ar) * d.lda + acl;
    const bf16* pBh = d.Bh + hof + (size_t)(n0 + ar) * d.ldb + acl;
    const bf16* pBl = d.Bl + hof + (size_t)(n0 + ar) * d.ldb + acl;
    const size_t a64 = (size_t)64 * d.lda;

    const uint32_t uAh = smem_u32(&sAh[0][0]), uAl = smem_u32(&sAl[0][0]);
    const uint32_t uBh = smem_u32(&sBh[0][0]), uBl = smem_u32(&sBl[0][0]);
    const int aR = mrow + (lane & 15), aC = (lane >> 4) * 8;
    const int bR = ncol + (lane & 7) + ((lane & 16) >> 1), bC = lane & 8;
    uint32_t adAh[2], adAl[2], adBh[2], adBl[2];
#pragma unroll
    for (int mt = 0; mt < 2; mt++) {
        adAh[mt] = uAh + ((aR + mt*16)*40 + aC)*2;
        adAl[mt] = uAl + ((aR + mt*16)*40 + aC)*2;
    }
#pragma unroll
    for (int pr = 0; pr < 2; pr++) {
        adBh[pr] = uBh + ((bR + pr*16)*40 + bC)*2;
        adBl[pr] = uBl + ((bR + pr*16)*40 + bC)*2;
    }

    float acc[2][4][4];
#pragma unroll
    for (int mt = 0; mt < 2; mt++)
#pragma unroll
        for (int nt = 0; nt < 4; nt++)
#pragma unroll
            for (int i = 0; i < 4; i++) acc[mt][nt][i] = 0.f;

    const int nkt = d.K >> 5;
    for (int kt = 0; kt < nkt; kt++) {
        const int k0 = kt * 32;
        uint4 vh0 = *(const uint4*)(pAh + k0);
        uint4 vh1 = *(const uint4*)(pAh + a64 + k0);
        uint4 vl0 = *(const uint4*)(pAl + k0);
        uint4 vl1 = *(const uint4*)(pAl + a64 + k0);
        uint4 wh  = *(const uint4*)(pBh + k0);
        uint4 wl  = *(const uint4*)(pBl + k0);
        __syncthreads();
        *(uint4*)&sAh[ar][acl]      = vh0;
        *(uint4*)&sAh[ar + 64][acl] = vh1;
        *(uint4*)&sAl[ar][acl]      = vl0;
        *(uint4*)&sAl[ar + 64][acl] = vl1;
        *(uint4*)&sBh[ar][acl]      = wh;
        *(uint4*)&sBl[ar][acl]      = wl;
        __syncthreads();
#pragma unroll
        for (int ks = 0; ks < 2; ks++) {
            uint32_t fAh[2][4], fAl[2][4], fBh[4][2], fBl[4][2];
#pragma unroll
            for (int mt = 0; mt < 2; mt++) {
                ldm4(fAh[mt], adAh[mt] + ks*32);
                ldm4(fAl[mt], adAl[mt] + ks*32);
            }
#pragma unroll
            for (int pr = 0; pr < 2; pr++) {
                uint32_t tb[4];
                ldm4(tb, adBh[pr] + ks*32);
                fBh[2*pr][0] = tb[0]; fBh[2*pr][1]   = tb[1];
                fBh[2*pr+1][0] = tb[2]; fBh[2*pr+1][1] = tb[3];
                ldm4(tb, adBl[pr] + ks*32);
                fBl[2*pr][0] = tb[0]; fBl[2*pr][1]   = tb[1];
                fBl[2*pr+1][0] = tb[2]; fBl[2*pr+1][1] = tb[3];
            }
#pragma unroll
            for (int mt = 0; mt < 2; mt++)
#pragma unroll
                for (int nt = 0; nt < 4; nt++) {
                    mma16816(acc[mt][nt], fAh[mt], fBh[nt]);
                    mma16816(acc[mt][nt], fAh[mt], fBl[nt]);
                    mma16816(acc[mt][nt], fAl[mt], fBh[nt]);
                }
        }
    }

#pragma unroll
    for (int mt = 0; mt < 2; mt++)
#pragma unroll
        for (int nt = 0; nt < 4; nt++) {
            int r = m0 + mrow + mt*16 + (lane >> 2);
            int c = n0 + ncol + nt*8 + (lane & 3)*2;
            float* a4 = acc[mt][nt];
            if (EPI == 1) {
                d.C[((size_t)r*NM + c)*8 + blockIdx.z]       = 1.f/(1.f+expf(-a4[0]));
                d.C[((size_t)r*NM + c+1)*8 + blockIdx.z]     = 1.f/(1.f+expf(-a4[1]));
                d.C[((size_t)(r+8)*NM + c)*8 + blockIdx.z]   = 1.f/(1.f+expf(-a4[2]));
                d.C[((size_t)(r+8)*NM + c+1)*8 + blockIdx.z] = 1.f/(1.f+expf(-a4[3]));
            } else {
                float b0v = d.bias ? d.bias[c] : 0.f;
                float b1v = d.bias ? d.bias[c+1] : 0.f;
                float v00 = d.scale*(a4[0]+b0v), v01 = d.scale*(a4[1]+b1v);
                float v10 = d.scale*(a4[2]+b0v), v11 = d.scale*(a4[3]+b1v);
                if (d.mode == 0) {
                    d.C[(size_t)r*d.ldc + c]       = v00;
                    d.C[(size_t)r*d.ldc + c+1]     = v01;
                    d.C[(size_t)(r+8)*d.ldc + c]   = v10;
                    d.C[(size_t)(r+8)*d.ldc + c+1] = v11;
                } else {
                    float vv[4] = {v00, v01, v10, v11};
                    size_t ix[4] = {(size_t)r*d.ldc + c, (size_t)r*d.ldc + c+1,
                                    (size_t)(r+8)*d.ldc + c, (size_t)(r+8)*d.ldc + c+1};
#pragma unroll
                    for (int u = 0; u < 4; u++) {
                        bf16 hh = __float2bfloat16(vv[u]);
                        d.Chi[ix[u]] = hh;
                        d.Clo[ix[u]] = __float2bfloat16(vv[u] - __bfloat162float(hh));
                    }
                }
            }
        }
}

// ---------------- conversion kernels ----------------------------------------
struct RMDesc { const float* a; const float* a2; bf16* hi; bf16* lo; int n4; };
struct RMParams { RMDesc d[4]; };
__global__ __launch_bounds__(256) void split_rm(RMParams p) {
    RMDesc d = p.d[blockIdx.z];
    int i = blockIdx.x * 256 + threadIdx.x;
    if (i >= d.n4) return;
    float4 x = ((const float4*)d.a)[i];
    if (d.a2) {
        float4 y = ((const float4*)d.a2)[i];
        x.x -= y.x; x.y -= y.y; x.z -= y.z; x.w -= y.w;
    }
    float v[4] = {x.x, x.y, x.z, x.w};
    __nv_bfloat162 H[2], L[2];
#pragma unroll
    for (int k = 0; k < 2; k++) {
        bf16 h0 = __float2bfloat16(v[2*k]), h1 = __float2bfloat16(v[2*k+1]);
        H[k] = __halves2bfloat162(h0, h1);
        L[k] = __halves2bfloat162(__float2bfloat16(v[2*k]   - __bfloat162float(h0)),
                                  __float2bfloat16(v[2*k+1] - __bfloat162float(h1)));
    }
    ((__nv_bfloat162*)d.hi)[i*2] = H[0]; ((__nv_bfloat162*)d.hi)[i*2+1] = H[1];
    ((__nv_bfloat162*)d.lo)[i*2] = L[0]; ((__nv_bfloat162*)d.lo)[i*2+1] = L[1];
}

struct TRDesc { const float* src; bf16* hi; bf16* lo; int K, N; };
struct TRParams { TRDesc d[8]; };
__global__ void split_tr(TRParams p) {
    TRDesc d = p.d[blockIdx.z];
    int n0 = blockIdx.x * 32, k0 = blockIdx.y * 32;
    if (n0 >= d.N || k0 >= d.K) return;
    __shared__ float tl[32][33];
    int tx = threadIdx.x, ty = threadIdx.y;
#pragma unroll
    for (int r = 0; r < 4; r++)
        tl[ty + r*8][tx] = d.src[(size_t)(k0 + ty + r*8) * d.N + n0 + tx];
    __syncthreads();
#pragma unroll
    for (int r = 0; r < 4; r++) {
        int n = n0 + ty + r*8, k = k0 + tx;
        float x = tl[tx][ty + r*8];
        bf16 h = __float2bfloat16(x);
        d.hi[(size_t)n * d.K + k] = h;
        d.lo[(size_t)n * d.K + k] = __float2bfloat16(x - __bfloat162float(h));
    }
}

// ---------------- parallel b01 ----------------------------------------------
__global__ void b01_part(const float* __restrict__ bo, const float* __restrict__ W1,
                         const float* __restrict__ biv, const float* __restrict__ W01,
                         float* __restrict__ part) {
    int b = blockIdx.x;
    int kc = (b % 24) * 32;
    const float* vec = (b < 24) ? bo  : biv;
    const float* Wm  = (b < 24) ? W1  : W01;
    int j = threadIdx.x;
    float s = 0.f;
#pragma unroll
    for (int k = 0; k < 32; k++)
        s = fmaf(vec[kc + k], Wm[(size_t)(kc + k)*256 + j], s);
    part[b*256 + j] = s;
}
__global__ void b01_final(const float* __restrict__ part, const float* __restrict__ b1,
                          float* __restrict__ b01) {
    int j = threadIdx.x;
    float s = b1[j];
#pragma unroll
    for (int i = 0; i < 48; i++) s += part[i*256 + j];
    b01[j] = s;
}

__global__ void reduce_kernel(const float* __restrict__ At, const float* __restrict__ b01,
                              float* __restrict__ Bm) {
    int m = blockIdx.x, j = threadIdx.x;
    float s = b01[j];
#pragma unroll
    for (int h = 0; h < 8; h++) s += At[(size_t)m*2048 + h*256 + j];
    Bm[(size_t)m*256 + j] = s;
}

// ---------------- fused tail: h-combine (SIMT) + h@W2 (tensor cores) --------
__global__ __launch_bounds__(256) void fuse2(
    const float* __restrict__ Ah_g, const float* __restrict__ Bm_g,
    const float* __restrict__ wbuf, const bf16* __restrict__ W2Th,
    const bf16* __restrict__ W2Tl, const float* __restrict__ b2,
    const float* __restrict__ W3, const float* __restrict__ b3,
    float* __restrict__ out) {

    __shared__ __align__(16) bf16 sHh[128*40], sHl[128*40];
    __shared__ __align__(16) bf16 sWh[64*40],  sWl[64*40];
    __shared__ __align__(16) float sA[8][32];
    __shared__ float sB[32];
    __shared__ float sb2[64], sW3[64], sb3;

    const int m = blockIdx.x, t = threadIdx.x, lane = t & 31, w = t >> 5;
    if (t < 64) { sb2[t] = b2[t]; sW3[t] = W3[t]; }
    if (t == 0) sb3 = b3[0];

    const int rn = t & 127, jh = t >> 7;          // row-in-half, j-subchunk
    const uint32_t uHh = smem_u32(sHh), uHl = smem_u32(sHl);
    const uint32_t uWh = smem_u32(sWh), uWl = smem_u32(sWl);
    const uint32_t adAh = uHh + ((w*16 + (lane & 15))*40 + (lane >> 4)*8)*2;
    const uint32_t adAl = uHl + ((w*16 + (lane & 15))*40 + (lane >> 4)*8)*2;
    const int bR = (lane & 7) + ((lane & 16) >> 1), bC = lane & 8;
    const int sh8 = t >> 5, sj = t & 31;          // sA staging coords
    const int wn = t >> 2, wseg = t & 3;          // W2T staging coords

    for (int half = 0; half < 2; half++) {
        const int n = half*128 + rn;
        const float4* wp = (const float4*)(wbuf + ((size_t)n*NM + m)*8);
        float4 wA = wp[0], wB = wp[1];
        ull wd[8];
        DUP2(wd[0], wA.x); DUP2(wd[1], wA.y); DUP2(wd[2], wA.z); DUP2(wd[3], wA.w);
        DUP2(wd[4], wB.x); DUP2(wd[5], wB.y); DUP2(wd[6], wB.z); DUP2(wd[7], wB.w);

        float acc[8][4];
#pragma unroll
        for (int nt = 0; nt < 8; nt++)
#pragma unroll
            for (int i = 0; i < 4; i++) acc[nt][i] = 0.f;

        for (int jc = 0; jc < 8; jc++) {
            const int j0 = jc * 32;
            __syncthreads();
            sA[sh8][sj] = Ah_g[(size_t)m*2048 + sh8*256 + j0 + sj];
            if (t < 32) sB[t] = Bm_g[(size_t)m*256 + j0 + t];
            *(uint4*)&sWh[wn*40 + wseg*8] = *(const uint4*)&W2Th[wn*256 + j0 + wseg*8];
            *(uint4*)&sWl[wn*40 + wseg*8] = *(const uint4*)&W2Tl[wn*256 + j0 + wseg*8];
            __syncthreads();

            // h-combine for 16 j's (j = j0 + jh*16 + [0..15])
            ull hacc[8];
#pragma unroll
            for (int i = 0; i < 8; i++) hacc[i] = *(const ull*)&sB[jh*16 + 2*i];
#pragma unroll
            for (int h8 = 0; h8 < 8; h8++)
#pragma unroll
                for (int i = 0; i < 8; i++)
                    FMA2(hacc[i], wd[h8], *(const ull*)&sA[h8][jh*16 + 2*i]);
            uint32_t hp[8], lp[8];
#pragma unroll
            for (int i = 0; i < 8; i++) {
                float f0, f1;
                UNPK2(f0, f1, hacc[i]);
                f0 = fmaxf(f0, 0.f); f1 = fmaxf(f1, 0.f);
                bf16 h0 = __float2bfloat16(f0), h1 = __float2bfloat16(f1);
                bf16 l0 = __float2bfloat16(f0 - __bfloat162float(h0));
                bf16 l1 = __float2bfloat16(f1 - __bfloat162float(h1));
                __nv_bfloat162 hx = __halves2bfloat162(h0, h1);
                __nv_bfloat162 lx = __halves2bfloat162(l0, l1);
                hp[i] = *(uint32_t*)&hx;
                lp[i] = *(uint32_t*)&lx;
            }
            {
                bf16* dsth = &sHh[rn*40 + jh*16];
                bf16* dstl = &sHl[rn*40 + jh*16];
                *(uint4*)dsth       = make_uint4(hp[0], hp[1], hp[2], hp[3]);
                *(uint4*)(dsth + 8) = make_uint4(hp[4], hp[5], hp[6], hp[7]);
                *(uint4*)dstl       = make_uint4(lp[0], lp[1], lp[2], lp[3]);
                *(uint4*)(dstl + 8) = make_uint4(lp[4], lp[5], lp[6], lp[7]);
            }
            __syncthreads();

#pragma unroll
            for (int ks = 0; ks < 2; ks++) {
                uint32_t fAh[4], fAl[4], fBh[8][2], fBl[8][2];
                ldm4(fAh, adAh + ks*32);
                ldm4(fAl, adAl + ks*32);
#pragma unroll
                for (int pr = 0; pr < 4; pr++) {
                    uint32_t tb[4];
                    ldm4(tb, uWh + ((pr*16 + bR)*40 + bC)*2 + ks*32);
                    fBh[2*pr][0] = tb[0]; fBh[2*pr][1]   = tb[1];
                    fBh[2*pr+1][0] = tb[2]; fBh[2*pr+1][1] = tb[3];
                    ldm4(tb, uWl + ((pr*16 + bR)*40 + bC)*2 + ks*32);
                    fBl[2*pr][0] = tb[0]; fBl[2*pr][1]   = tb[1];
                    fBl[2*pr+1][0] = tb[2]; fBl[2*pr+1][1] = tb[3];
                }
#pragma unroll
                for (int nt = 0; nt < 8; nt++) {
                    mma16816(acc[nt], fAh, fBh[nt]);
                    mma16816(acc[nt], fAh, fBl[nt]);
                    mma16816(acc[nt], fAl, fBh[nt]);
                }
            }
        }

        // epilogue: relu(acc + b2) . W3, quad-reduce, tanh
        float s0 = 0.f, s1 = 0.f;
#pragma unroll
        for (int nt = 0; nt < 8; nt++) {
            int c0 = nt*8 + 2*(lane & 3);
            float w30 = sW3[c0], w31 = sW3[c0+1];
            float bb0 = sb2[c0], bb1 = sb2[c0+1];
            s0 = fmaf(fmaxf(acc[nt][0] + bb0, 0.f), w30, s0);
            s0 = fmaf(fmaxf(acc[nt][1] + bb1, 0.f), w31, s0);
            s1 = fmaf(fmaxf(acc[nt][2] + bb0, 0.f), w30, s1);
            s1 = fmaf(fmaxf(acc[nt][3] + bb1, 0.f), w31, s1);
        }
        s0 += __shfl_xor_sync(0xFFFFFFFF, s0, 1);
        s0 += __shfl_xor_sync(0xFFFFFFFF, s0, 2);
        s1 += __shfl_xor_sync(0xFFFFFFFF, s1, 1);
        s1 += __shfl_xor_sync(0xFFFFFFFF, s1, 2);
        if ((lane & 3) == 0) {
            int r0 = half*128 + w*16 + (lane >> 2);
            out[(size_t)r0*NM + m]     = 0.5f * tanhf(s0 + sb3);
            out[(size_t)(r0+8)*NM + m] = 0.5f * tanhf(s1 + sb3);
        }
    }
}

// ---------------- launch ----------------------------------------------------
extern "C" void kernel_launch(void* const* d_in, const int* in_sizes, int n_in,
                              void* d_out, int out_size) {
    const float* Q   = (const float*)d_in[0];
    const float* IMG = (const float*)d_in[1];
    const float* TGT = (const float*)d_in[2];
    const float* Wq  = (const float*)d_in[3];
    const float* bq  = (const float*)d_in[4];
    const float* Wi  = (const float*)d_in[5];
    const float* bi  = (const float*)d_in[6];
    const float* Wt  = (const float*)d_in[7];
    const float* bt  = (const float*)d_in[8];
    const float* Wiq = (const float*)d_in[9];
    const float* biq = (const float*)d_in[10];
    const float* Wik = (const float*)d_in[11];
    const float* Wiv = (const float*)d_in[13];
    const float* biv = (const float*)d_in[14];
    const float* Wo  = (const float*)d_in[15];
    const float* bo  = (const float*)d_in[16];
    const float* W1  = (const float*)d_in[17];
    const float* b1  = (const float*)d_in[18];
    const float* W2  = (const float*)d_in[19];
    const float* b2  = (const float*)d_in[20];
    const float* W3  = (const float*)d_in[21];
    const float* b3  = (const float*)d_in[22];
    float* out = (float*)d_out;

    float* F; bf16* B;
    cudaGetSymbolAddress((void**)&F, g_f);
    cudaGetSymbolAddress((void**)&B, g_b);
    float *ip = F+F_ip, *tp = F+F_tp;
    float *W01 = F+F_W01, *b01 = F+F_b01, *part = F+F_part;
    float *Ah = F+F_Ah, *At = F+F_At, *Bm = F+F_Bm, *wb = F+F_w;

#define HI(off) (B + (off))
#define LO(off, sz) (B + (off) + (sz))
    const float scale = 1.0f / sqrtf(96.0f);

    // C1: split row-major inputs
    RMParams rm1 = {};
    rm1.d[0] = {Q,   0, HI(B_Qs),   LO(B_Qs,   256*768), 256*768/4};
    rm1.d[1] = {IMG, 0, HI(B_IMGs), LO(B_IMGs, 512*768), 512*768/4};
    rm1.d[2] = {TGT, 0, HI(B_TGTs), LO(B_TGTs, 512*768), 512*768/4};
    rm1.d[3] = {Wo,  0, HI(B_Wos),  LO(B_Wos,  768*768), 768*768/4};
    split_rm<<<dim3(576, 1, 4), 256>>>(rm1);

    // C2: transpose+split weights (incl. W2^T for fuse2)
    TRParams tr1 = {};
    tr1.d[0] = {Wq,  HI(B_WqT),  LO(B_WqT,  768*768), 768, 768};
    tr1.d[1] = {Wi,  HI(B_WiT),  LO(B_WiT,  768*768), 768, 768};
    tr1.d[2] = {Wt,  HI(B_WtT),  LO(B_WtT,  768*768), 768, 768};
    tr1.d[3] = {Wiq, HI(B_WiqT), LO(B_WiqT, 768*768), 768, 768};
    tr1.d[4] = {Wik, HI(B_WikT), LO(B_WikT, 768*768), 768, 768};
    tr1.d[5] = {Wiv, HI(B_WivT), LO(B_WivT, 768*768), 768, 768};
    tr1.d[6] = {W1,  HI(B_W1T),  LO(B_W1T,  256*768), 768, 256};
    tr1.d[7] = {W2,  HI(B_W2T),  LO(B_W2T,  64*256),  256, 64};
    split_tr<<<dim3(24, 24, 8), dim3(32, 8)>>>(tr1);

    // L1: stage-1 projections (q split-direct) + W01 = Wo@W1
    TCParams p1 = {};
    p1.d[0] = {HI(B_Qs),   LO(B_Qs,  256*768), HI(B_WqT), LO(B_WqT, 768*768), bq, 0,
               HI(B_qs), LO(B_qs, 256*768), 768, 768, 768, 256, 768, 768, 1.f, 2};
    p1.d[1] = {HI(B_IMGs), LO(B_IMGs,512*768), HI(B_WiT), LO(B_WiT, 768*768), bi, ip,
               0, 0, 768, 768, 768, 512, 768, 768, 1.f, 0};
    p1.d[2] = {HI(B_TGTs), LO(B_TGTs,512*768), HI(B_WtT), LO(B_WtT, 768*768), bt, tp,
               0, 0, 768, 768, 768, 512, 768, 768, 1.f, 0};
    p1.d[3] = {HI(B_Wos),  LO(B_Wos, 768*768), HI(B_W1T), LO(B_W1T, 256*768), 0, W01,
               0, 0, 768, 768, 256, 768, 256, 768, 1.f, 0};
    mma_gemm<0><<<dim3(12, 6, 4), 256>>>(p1);

    // parallel b01 = b1 + bo@W1 + biv@W01
    b01_part<<<48, 256>>>(bo, W1, biv, W01, part);
    b01_final<<<1, 256>>>(part, b1, b01);

    // C3: split stage-1 activations (ip-tp diff, tp)
    RMParams rm2 = {};
    rm2.d[0] = {ip, tp, HI(B_dps), LO(B_dps, 512*768), 512*768/4};
    rm2.d[1] = {tp, 0,  HI(B_tps), LO(B_tps, 512*768), 512*768/4};
    split_rm<<<dim3(384, 1, 2), 256>>>(rm2);

    // C2b: W01^T split
    TRParams tr2 = {};
    tr2.d[0] = {W01, HI(B_W01T), LO(B_W01T, 256*768), 768, 256};
    split_tr<<<dim3(8, 24, 1), dim3(32, 8)>>>(tr2);

    // L2: qh, kd, vd, vt — all written directly as bf16 splits
    TCParams p2 = {};
    p2.d[0] = {HI(B_qs),  LO(B_qs, 256*768), HI(B_WiqT), LO(B_WiqT, 768*768), biq, 0,
               HI(B_qhs), LO(B_qhs, 256*768), 768, 768, 768, 256, 768, 768, scale, 2};
    p2.d[1] = {HI(B_dps), LO(B_dps,512*768), HI(B_WikT), LO(B_WikT, 768*768), 0, 0,
               HI(B_kds), LO(B_kds, 512*768), 768, 768, 768, 512, 768, 768, 1.f, 2};
    p2.d[2] = {HI(B_dps), LO(B_dps,512*768), HI(B_WivT), LO(B_WivT, 768*768), 0, 0,
               HI(B_vds), LO(B_vds, 512*768), 768, 768, 768, 512, 768, 768, 1.f, 2};
    p2.d[3] = {HI(B_tps), LO(B_tps,512*768), HI(B_WivT), LO(B_WivT, 768*768), 0, 0,
               HI(B_vts), LO(B_vts, 512*768), 768, 768, 768, 512, 768, 768, 1.f, 2};
    mma_gemm<0><<<dim3(12, 4, 4), 256>>>(p2);

    // L4: attention weights (per-head K=96, sigmoid epilogue scatter)
    TCParams pl = {};
    pl.d[0] = {HI(B_qhs), LO(B_qhs, 256*768), HI(B_kds), LO(B_kds, 512*768), 0, wb,
               0, 0, 768, 768, 0, 256, 512, 96, 1.f, 0};
    mma_gemm<1><<<dim3(8, 2, 8), 256>>>(pl);

    // L3: per-head Ah/At = vd_h/vt_h @ W01_h  (K=96)
    TCParams p3 = {};
    for (int h = 0; h < 8; h++) {
        p3.d[h]   = {HI(B_vds) + h*96, LO(B_vds, 512*768) + h*96,
                     HI(B_W01T) + h*96, LO(B_W01T, 256*768) + h*96, 0,
                     Ah + h*256, 0, 0, 768, 768, 2048, 512, 256, 96, 1.f, 0};
        p3.d[8+h] = {HI(B_vts) + h*96, LO(B_vts, 512*768) + h*96,
                     HI(B_W01T) + h*96, LO(B_W01T, 256*768) + h*96, 0,
                     At + h*256, 0, 0, 768, 768, 2048, 512, 256, 96, 1.f, 0};
    }
    mma_gemm<0><<<dim3(4, 4, 16), 256>>>(p3);

    reduce_kernel<<<NM, 256>>>(At, b01, Bm);

    // L5: tensor-core fused tail
    fuse2<<<NM, 256>>>(Ah, Bm, wb, HI(B_W2T), LO(B_W2T, 64*256),
                       b2, W3, b3, out);
}